// round 12
// baseline (speedup 1.0000x reference)
#include <cuda_runtime.h>
#include <cuda_fp16.h>
#include <cuda_bf16.h>
#include <cstdint>

#define BB   8
#define TLEN 32000
#define RES  64
#define GATE 128
#define SKC  64
#define CINC 80
#define NL   30
#define OUTC 256
#define TILE 128      /* head kernel time tile */
#define NTH  256      /* head kernel threads */
#define TT   128      /* layer time tile */
#define NTL  512      /* layer kernel threads (16 warps) */

#define AST2 68       /* ACT stride in half2 units (136 halves, conflict-free) */
#define GST  132      /* gate staging stride (floats) */
#define ZST2 36       /* Z stride in half2 units */
#define SM_Z 67584    /* max(ACT 34816, G 67584) */
#define SM_Y0 (SM_Z + TT*ZST2*4)        /* 86016: y0s [128][8] floats */
#define SM_WT (SM_Y0 + 4096)            /* 90112: wt float4[128] */
#define SM_WO (SM_WT + 2048)            /* 92160: wo int[128] */
#define SMEM_LAYER (SM_WO + 512)        /* 92672 */
#define SMEM_FINAL (RES*TILE*2*4)       /* 65536 */
#define SMEM_Y0GEMM (128*80*4 + 80*100*4)  /* 72960 */

typedef unsigned int u32;
typedef unsigned long long ull;

/* ---------------- device scratch ---------------- */
__device__ __align__(256) float g_hA[BB*(size_t)TLEN*RES];    // [b][t][64]
__device__ __align__(256) float g_hB[BB*(size_t)TLEN*RES];
__device__ __align__(256) float g_skip[BB*(size_t)TLEN*SKC];  // [b][t][64]
__device__ __align__(256) float g_cA[BB*CINC*400];            // [b][80][400]
__device__ __align__(256) float g_y0[BB*NL*128*400];          // [b][l][ch][400]
__device__ __align__(256) float4 g_wt4[TLEN];                 // 4-tap upsample weights
__device__ __align__(256) int   g_wbase[TLEN];                // base frame per t
__device__ __align__(256) u32   g_W1pk[NL*8192];   // fp16 frag-packed: [l][ks8][nt16][lane32][2]
__device__ __align__(256) u32   g_W2pk[NL*4096];   // [l][ks4][nt16][lane32][2]
__device__ __align__(256) float g_fwT[OUTC*RES];   // first_w^T + bias
__device__ int g_xflag;

/* ---------------- helpers ---------------- */
__device__ __forceinline__ u32 h2bits(float a, float b) {
    __half2 h = __floats2half2_rn(a, b);
    return *(u32*)&h;
}
__device__ __forceinline__ void mma_f16(float c[4], const u32 a[4], const u32 b[2]) {
    asm volatile("mma.sync.aligned.m16n8k16.row.col.f32.f16.f16.f32 "
        "{%0,%1,%2,%3}, {%4,%5,%6,%7}, {%8,%9}, {%0,%1,%2,%3};"
        : "+f"(c[0]), "+f"(c[1]), "+f"(c[2]), "+f"(c[3])
        : "r"(a[0]), "r"(a[1]), "r"(a[2]), "r"(a[3]), "r"(b[0]), "r"(b[1]));
}
__device__ __forceinline__ float sigf(float x) {
    return __fdividef(1.f, 1.f + __expf(-x));
}
__device__ __forceinline__ float tanhfast(float x) {
    return 2.f * sigf(2.f * x) - 1.f;
}
__device__ __forceinline__ void ffma2(ull& acc, ull ab, ull h2) {
    asm("fma.rn.f32x2 %0, %1, %2, %0;" : "+l"(acc) : "l"(ab), "l"(h2));
}
__device__ __forceinline__ ull pack2(float x) {
    ull r; asm("mov.b64 %0, {%1, %1};" : "=l"(r) : "f"(x)); return r;
}
__device__ __forceinline__ float2 unpack2(ull v) {
    float2 r; asm("mov.b64 {%0, %1}, %2;" : "=f"(r.x), "=f"(r.y) : "l"(v)); return r;
}

/* ---------------- dtype detect ---------------- */
__global__ void k_detect(const unsigned* __restrict__ xu) {
    __shared__ int s_any;
    if (threadIdx.x == 0) s_any = 0;
    __syncthreads();
    int any = 0;
    for (int i = 1 + 2*threadIdx.x; i < BB*TLEN; i += 2*blockDim.x)
        any |= (xu[i] != 0u);
    if (any) atomicOr(&s_any, 1);
    __syncthreads();
    if (threadIdx.x == 0) g_xflag = s_any;
}

/* ---------------- weight prep ---------------- */
__global__ void k_prep_fwt(const float* __restrict__ fw, const float* __restrict__ fb) {
    int i = blockIdx.x*blockDim.x + threadIdx.x;
    if (i >= OUTC*RES) return;
    int xi = i >> 6, o = i & 63;
    g_fwT[i] = fw[o*OUTC + xi] + fb[o];
}

__global__ void k_prep_w1(const float* __restrict__ conv_w) {
    int i = blockIdx.x*blockDim.x + threadIdx.x;
    if (i >= NL*8192) return;
    int l = i / 8192, r = i % 8192;
    int ks = r >> 10, rem = r & 1023;
    int nt = rem >> 6, rem2 = rem & 63;
    int lane = rem2 >> 1, reg = rem2 & 1;
    int k0 = ks*16 + 2*(lane & 3) + 8*reg;   // 0..127 (even)
    int n  = nt*8 + (lane >> 2);
    float f0, f1;
    if (k0 < 64) {
        f0 = conv_w[((l*GATE + n)*RES + k0)*2 + 0];
        f1 = conv_w[((l*GATE + n)*RES + k0 + 1)*2 + 0];
    } else {
        f0 = conv_w[((l*GATE + n)*RES + (k0-64))*2 + 1];
        f1 = conv_w[((l*GATE + n)*RES + (k0-63))*2 + 1];
    }
    g_W1pk[i] = h2bits(f0, f1);
}

__global__ void k_prep_w2(const float* __restrict__ skip_w, const float* __restrict__ out_w) {
    int i = blockIdx.x*blockDim.x + threadIdx.x;
    if (i >= NL*4096) return;
    int l = i / 4096, r = i % 4096;
    int ks = r >> 10, rem = r & 1023;
    int nt = rem >> 6, rem2 = rem & 63;
    int lane = rem2 >> 1, reg = rem2 & 1;
    int k0 = ks*16 + 2*(lane & 3) + 8*reg;   // 0..63 (even)
    int n  = nt*8 + (lane >> 2);
    float f0 = (n < 64) ? skip_w[(l*SKC + n)*64 + k0]
                        : out_w[(l*RES + (n-64))*64 + k0];
    float f1 = (n < 64) ? skip_w[(l*SKC + n)*64 + k0 + 1]
                        : out_w[(l*RES + (n-64))*64 + k0 + 1];
    g_W2pk[i] = h2bits(f0, f1);
}

/* ---- 4-tap composite upsample weights (exact linear impulse of upB+upC) ---- */
__global__ void k_prep_wtab() {
    int t = blockIdx.x*blockDim.x + threadIdx.x;
    if (t >= TLEN) return;
    int lo = t-8 < 0 ? 0 : t-8;
    int hi = t+8 > TLEN-1 ? TLEN-1 : t+8;
    int fmin = 400;
    for (int v = lo; v <= hi; ++v) {
        int tau = v >> 3;
        int jlo = tau-10 < 0 ? 0 : tau-10;
        int f0 = jlo/10;
        if (f0 < fmin) fmin = f0;
    }
    float w0=0.f, w1=0.f, w2=0.f, w3=0.f;
    const float sc = 1.f/(17.f*21.f);
    for (int v = lo; v <= hi; ++v) {
        int tau = v >> 3;
        int jlo = tau-10 < 0 ? 0 : tau-10;
        int jhi = tau+10 > 3999 ? 3999 : tau+10;
        for (int j = jlo; j <= jhi; ++j) {
            int q = j/10 - fmin;
            if (q == 0) w0 += sc;
            else if (q == 1) w1 += sc;
            else if (q == 2) w2 += sc;
            else w3 += sc;
        }
    }
    g_wt4[t] = make_float4(w0, w1, w2, w3);
    g_wbase[t] = fmin;
}

/* ---- y0[b][l] = cond_w[l] @ cA[b]  ([128][400] per (b,l)) ---- */
__global__ void __launch_bounds__(512) k_prep_y0(const float* __restrict__ cond_w) {
    extern __shared__ float sy[];
    float* s_cw = sy;            // [128][80]
    float* s_ca = sy + 128*80;   // [80][100]
    int bl = blockIdx.x;
    int b = bl / NL, l = bl % NL;
    int tid = threadIdx.x;

    for (int i = tid; i < 128*80; i += 512)
        s_cw[i] = cond_w[l*GATE*CINC + i];

    for (int ft = 0; ft < 4; ++ft) {
        __syncthreads();
        for (int i = tid; i < 80*100; i += 512) {
            int ch = i / 100, f = i % 100;
            s_ca[i] = g_cA[(b*CINC + ch)*400 + ft*100 + f];
        }
        __syncthreads();
        for (int i = tid; i < 128*100; i += 512) {
            int ch = i / 100, f = i % 100;
            const float* wr = s_cw + ch*80;
            const float* cr = s_ca + f;
            float s = 0.f;
            #pragma unroll 8
            for (int k = 0; k < 80; ++k) s += wr[k] * cr[k*100];
            g_y0[((size_t)(b*NL + l)*128 + ch)*400 + ft*100 + f] = s;
        }
    }
}

/* ---------------- first conv + skip reset ([b][t][ch]) ---------------- */
__global__ void k_first(const void* __restrict__ xraw) {
    int idx = blockIdx.x*blockDim.x + threadIdx.x;
    if (idx >= BB*TLEN*16) return;
    int q = idx & 15;
    int g = idx >> 4;
    int t = g % TLEN, b = g / TLEN;
    int xi = g_xflag ? ((const int*)xraw)[g]
                     : (int)(((const long long*)xraw)[g]);
    float4 v = ((const float4*)(g_fwT + xi*64))[q];
    size_t off = ((size_t)b*TLEN + t)*64 + q*4;
    *(float4*)(g_hA + off) = v;
    *(float4*)(g_skip + off) = make_float4(0.f, 0.f, 0.f, 0.f);
}

/* ---------------- conditioning 1x1 (frame domain) ---------------- */
__global__ void k_upA(const float* __restrict__ cond, const float* __restrict__ cin_w) {
    int i = blockIdx.x*blockDim.x + threadIdx.x;
    if (i >= BB*CINC*400) return;
    int f = i % 400, o = (i/400) % CINC, b = i / (CINC*400);
    const float* cp = cond + b*CINC*400 + f;
    const float* wp = cin_w + o*CINC;
    float s = 0.f;
    #pragma unroll 8
    for (int k = 0; k < CINC; ++k) s += wp[k] * cp[k*400];
    g_cA[i] = s;
}

/* ---------------- fp16 mma.sync layer kernel (occ 2, K=128) ---------------- */
__global__ void __launch_bounds__(NTL, 2) k_layer(int l, int d,
        const float* __restrict__ conv_b,
        const float* __restrict__ skip_b,
        const float* __restrict__ out_b) {
    extern __shared__ __align__(16) char smx[];
    u32*   ACT2 = (u32*)smx;               // [128][AST2] half2; becomes G after stage1
    float* G    = (float*)smx;             // [128][GST]
    u32*   Z2   = (u32*)(smx + SM_Z);      // [128][ZST2] half2
    float* s_y0 = (float*)(smx + SM_Y0);   // [128][8]
    float4* s_wt = (float4*)(smx + SM_WT); // [128]
    int*   s_wo = (int*)(smx + SM_WO);     // [128]

    int tid = threadIdx.x, lane = tid & 31, wid = tid >> 5;
    int gid = lane >> 2, tig = lane & 3;
    int tg = wid & 3, cg = wid >> 2;       // 4 time-groups x 4 channel-groups
    int b = blockIdx.y, t0 = blockIdx.x * TT;

    const float* hin  = ((l & 1) ? g_hB : g_hA) + (size_t)b*TLEN*64;
    float*       hout = ((l & 1) ? g_hA : g_hB) + (size_t)b*TLEN*64;

    int fbase = g_wbase[t0];

    /* ---- preload y0 frames + weight table ---- */
    if (tid < 128) {
        int t = t0 + tid;
        s_wt[tid] = g_wt4[t];
        s_wo[tid] = g_wbase[t] - fbase;
    }
    {
        const float* y0p = g_y0 + (size_t)(b*NL + l)*128*400;
        for (int i = tid; i < 128*8; i += NTL) {
            int ch = i >> 3, q = i & 7;
            int f = fbase + q;
            s_y0[i] = (f < 400) ? y0p[ch*400 + f] : 0.f;
        }
    }

    /* ---- assemble ACT [t][k<128 halves]: hd(64) | h(64), batched LDG ---- */
    #pragma unroll
    for (int it = 0; it < 4; ++it) {
        int idx = tid + it*NTL;
        int t = idx >> 4, q = idx & 15;
        int ts = t0 + t - d;
        float4 v = make_float4(0.f, 0.f, 0.f, 0.f);
        if (ts >= 0) v = *(const float4*)(hin + (size_t)ts*64 + q*4);
        *(uint2*)(ACT2 + t*AST2 + q*2) =
            make_uint2(h2bits(v.x, v.y), h2bits(v.z, v.w));
    }
    #pragma unroll
    for (int it = 0; it < 4; ++it) {
        int idx = tid + it*NTL;
        int t = idx >> 4, q = idx & 15;
        float4 v = *(const float4*)(hin + (size_t)(t0 + t)*64 + q*4);
        *(uint2*)(ACT2 + t*AST2 + (q + 16)*2) =
            make_uint2(h2bits(v.x, v.y), h2bits(v.z, v.w));
    }
    __syncthreads();

    /* ---- stage 1: D1[128 t][128 gate ch], K=128 (8 k-steps) ---- */
    float acc[2][4][4];
    #pragma unroll
    for (int i = 0; i < 2; ++i)
        #pragma unroll
        for (int j = 0; j < 4; ++j)
            #pragma unroll
            for (int r = 0; r < 4; ++r) acc[i][j][r] = 0.f;

    const u32* W1p = g_W1pk + (size_t)l*8192;
    #pragma unroll 1
    for (int ks = 0; ks < 8; ++ks) {
        u32 a[2][4];
        int kk = ks*8 + tig;               // half2 index
        #pragma unroll
        for (int i = 0; i < 2; ++i) {
            int m = (tg*2 + i)*16 + gid;
            a[i][0] = ACT2[m*AST2 + kk];
            a[i][1] = ACT2[(m+8)*AST2 + kk];
            a[i][2] = ACT2[m*AST2 + kk + 4];
            a[i][3] = ACT2[(m+8)*AST2 + kk + 4];
        }
        #pragma unroll
        for (int j = 0; j < 4; ++j) {
            int nt = cg*4 + j;
            uint2 bv = __ldg((const uint2*)(W1p + ((ks*16 + nt)*32 + lane)*2));
            u32 bb[2] = {bv.x, bv.y};
            mma_f16(acc[0][j], a[0], bb);
            mma_f16(acc[1][j], a[1], bb);
        }
    }
    __syncthreads();   /* all ACT reads complete before G overwrite */

    /* ---- epilogue 1: write gates to G ---- */
    #pragma unroll
    for (int i = 0; i < 2; ++i) {
        int m0 = (tg*2 + i)*16 + gid;
        #pragma unroll
        for (int j = 0; j < 4; ++j) {
            int n0 = cg*32 + j*8 + 2*tig;
            *(float2*)&G[m0*GST + n0]     = make_float2(acc[i][j][0], acc[i][j][1]);
            *(float2*)&G[(m0+8)*GST + n0] = make_float2(acc[i][j][2], acc[i][j][3]);
        }
    }
    __syncthreads();

    /* ---- gate: z = tanh(a+cond_a)*sigmoid(b+cond_b) -> Z (half2) ---- */
    for (int idx = tid; idx < TT*32; idx += NTL) {
        int t = idx >> 5, c2 = idx & 31;
        int ch = c2*2;
        float4 w = s_wt[t];
        int ob = s_wo[t];
        const float* ya0 = s_y0 + ch*8 + ob;
        const float* ya1 = s_y0 + (ch+1)*8 + ob;
        const float* yb0 = s_y0 + (ch+64)*8 + ob;
        const float* yb1 = s_y0 + (ch+65)*8 + ob;
        float ca0 = w.x*ya0[0] + w.y*ya0[1] + w.z*ya0[2] + w.w*ya0[3];
        float ca1 = w.x*ya1[0] + w.y*ya1[1] + w.z*ya1[2] + w.w*ya1[3];
        float cb0 = w.x*yb0[0] + w.y*yb0[1] + w.z*yb0[2] + w.w*yb0[3];
        float cb1 = w.x*yb1[0] + w.y*yb1[1] + w.z*yb1[2] + w.w*yb1[3];
        float a0 = G[t*GST + ch]     + conv_b[ch]     + ca0;
        float a1 = G[t*GST + ch + 1] + conv_b[ch + 1] + ca1;
        float b0 = G[t*GST + 64 + ch]     + conv_b[64 + ch]     + cb0;
        float b1 = G[t*GST + 64 + ch + 1] + conv_b[64 + ch + 1] + cb1;
        Z2[t*ZST2 + c2] = h2bits(tanhfast(a0) * sigf(b0),
                                 tanhfast(a1) * sigf(b1));
    }
    __syncthreads();

    /* ---- stage 2: D2[128 t][skip64|out64], K=64 (4 k-steps) ---- */
    float acc2[2][4][4];
    #pragma unroll
    for (int i = 0; i < 2; ++i)
        #pragma unroll
        for (int j = 0; j < 4; ++j)
            #pragma unroll
            for (int r = 0; r < 4; ++r) acc2[i][j][r] = 0.f;

    const u32* W2p = g_W2pk + (size_t)l*4096;
    #pragma unroll
    for (int ks = 0; ks < 4; ++ks) {
        u32 a[2][4];
        int kk = ks*8 + tig;
        #pragma unroll
        for (int i = 0; i < 2; ++i) {
            int m = (tg*2 + i)*16 + gid;
            a[i][0] = Z2[m*ZST2 + kk];
            a[i][1] = Z2[(m+8)*ZST2 + kk];
            a[i][2] = Z2[m*ZST2 + kk + 4];
            a[i][3] = Z2[(m+8)*ZST2 + kk + 4];
        }
        #pragma unroll
        for (int j = 0; j < 4; ++j) {
            int nt = cg*4 + j;
            uint2 bv = __ldg((const uint2*)(W2p + ((ks*16 + nt)*32 + lane)*2));
            u32 bb[2] = {bv.x, bv.y};
            mma_f16(acc2[0][j], a[0], bb);
            mma_f16(acc2[1][j], a[1], bb);
        }
    }

    /* ---- epilogue 2: skip RMW + residual h ---- */
    #pragma unroll
    for (int i = 0; i < 2; ++i) {
        int m0 = (tg*2 + i)*16 + gid;
        #pragma unroll
        for (int j = 0; j < 4; ++j) {
            int n0 = cg*32 + j*8 + 2*tig;
            #pragma unroll
            for (int h2 = 0; h2 < 2; ++h2) {
                int t = t0 + m0 + 8*h2;
                float v0 = acc2[i][j][2*h2], v1 = acc2[i][j][2*h2 + 1];
                if (n0 < 64) {
                    float2* sp = (float2*)&g_skip[((size_t)b*TLEN + t)*64 + n0];
                    float2 cur = *sp;
                    cur.x += v0 + skip_b[n0];
                    cur.y += v1 + skip_b[n0 + 1];
                    *sp = cur;
                } else {
                    int o = n0 - 64;
                    float2 hv = *(const float2*)&hin[(size_t)t*64 + o];
                    float2 r = make_float2(hv.x + v0 + out_b[o],
                                           hv.y + v1 + out_b[o + 1]);
                    *(float2*)&hout[(size_t)t*64 + o] = r;
                }
            }
        }
    }
}

/* ---------------- output head (FFMA2, transpose-load skip) ---------------- */
__global__ void __launch_bounds__(NTH) k_final(const float* __restrict__ w1,
                                               const float* __restrict__ b1,
                                               const float* __restrict__ w2,
                                               const float* __restrict__ b2,
                                               float* __restrict__ out) {
    extern __shared__ float sm[];
    float* sh_s = sm;              // relu(skips) [64][128]
    float* sh_y = sm + RES*TILE;   // relu(y1)    [64][128]
    int b = blockIdx.y, t0 = blockIdx.x * TILE, tid = threadIdx.x;

    for (int idx = tid; idx < 16*TILE; idx += NTH) {
        int t = idx & (TILE-1), q = idx >> 7;
        float4 v = *(const float4*)(g_skip + ((size_t)b*TLEN + t0 + t)*64 + q*4);
        sh_s[(q*4+0)*TILE + t] = fmaxf(v.x, 0.f);
        sh_s[(q*4+1)*TILE + t] = fmaxf(v.y, 0.f);
        sh_s[(q*4+2)*TILE + t] = fmaxf(v.z, 0.f);
        sh_s[(q*4+3)*TILE + t] = fmaxf(v.w, 0.f);
    }
    __syncthreads();

    int og = tid >> 3, tg = tid & 7;

    {
        ull a0[8], a1[8];
        ull c0 = pack2(b1[og*2]), c1 = pack2(b1[og*2+1]);
        #pragma unroll
        for (int j = 0; j < 8; ++j) { a0[j] = c0; a1[j] = c1; }
        #pragma unroll 4
        for (int r = 0; r < 64; ++r) {
            ull w0 = pack2(w1[(og*2+0)*64 + r]);
            ull w1v = pack2(w1[(og*2+1)*64 + r]);
            const ull* sv = (const ull*)(sh_s + r*TILE) + tg;
            #pragma unroll
            for (int j = 0; j < 8; ++j) {
                ull s = sv[j*8];
                ffma2(a0[j], w0, s);
                ffma2(a1[j], w1v, s);
            }
        }
        #pragma unroll
        for (int j = 0; j < 8; ++j) {
            float2 v0 = unpack2(a0[j]), v1 = unpack2(a1[j]);
            v0.x = fmaxf(v0.x, 0.f); v0.y = fmaxf(v0.y, 0.f);
            v1.x = fmaxf(v1.x, 0.f); v1.y = fmaxf(v1.y, 0.f);
            *(float2*)(sh_y + (og*2+0)*TILE + 2*(tg + 8*j)) = v0;
            *(float2*)(sh_y + (og*2+1)*TILE + 2*(tg + 8*j)) = v1;
        }
    }
    __syncthreads();

    #pragma unroll 1
    for (int p = 0; p < 2; ++p) {
        int ob = p*128 + og*4;
        ull acc[4][8];
        #pragma unroll
        for (int i = 0; i < 4; ++i) {
            ull bi = pack2(b2[ob + i]);
            #pragma unroll
            for (int j = 0; j < 8; ++j) acc[i][j] = bi;
        }
        #pragma unroll 4
        for (int r = 0; r < 64; ++r) {
            ull w0 = pack2(w2[(ob+0)*64 + r]);
            ull w1v = pack2(w2[(ob+1)*64 + r]);
            ull w2v = pack2(w2[(ob+2)*64 + r]);
            ull w3v = pack2(w2[(ob+3)*64 + r]);
            const ull* yv = (const ull*)(sh_y + r*TILE) + tg;
            #pragma unroll
            for (int j = 0; j < 8; ++j) {
                ull y = yv[j*8];
                ffma2(acc[0][j], w0, y);
                ffma2(acc[1][j], w1v, y);
                ffma2(acc[2][j], w2v, y);
                ffma2(acc[3][j], w3v, y);
            }
        }
        #pragma unroll
        for (int i = 0; i < 4; ++i) {
            float2* row = (float2*)(out + ((size_t)b*OUTC + ob + i)*TLEN + t0);
            #pragma unroll
            for (int j = 0; j < 8; ++j)
                row[tg + 8*j] = unpack2(acc[i][j]);
        }
    }
}

/* ---------------- launch ---------------- */
extern "C" void kernel_launch(void* const* d_in, const int* in_sizes, int n_in,
                              void* d_out, int out_size) {
    (void)in_sizes; (void)n_in; (void)out_size;
    const void*  x       = d_in[0];
    const float* cond    = (const float*)d_in[1];
    const float* first_w = (const float*)d_in[2];
    const float* first_b = (const float*)d_in[3];
    const float* cin_w   = (const float*)d_in[4];
    const float* conv_w  = (const float*)d_in[5];
    const float* conv_b  = (const float*)d_in[6];
    const float* cond_w  = (const float*)d_in[7];
    const float* skip_w  = (const float*)d_in[8];
    const float* skip_b  = (const float*)d_in[9];
    const float* out_w   = (const float*)d_in[10];
    const float* out_b   = (const float*)d_in[11];
    const float* l1w     = (const float*)d_in[12];
    const float* l1b     = (const float*)d_in[13];
    const float* l2w     = (const float*)d_in[14];
    const float* l2b     = (const float*)d_in[15];
    float* out = (float*)d_out;

    cudaFuncSetAttribute(k_layer, cudaFuncAttributeMaxDynamicSharedMemorySize, SMEM_LAYER);
    cudaFuncSetAttribute(k_final, cudaFuncAttributeMaxDynamicSharedMemorySize, SMEM_FINAL);
    cudaFuncSetAttribute(k_prep_y0, cudaFuncAttributeMaxDynamicSharedMemorySize, SMEM_Y0GEMM);

    k_detect<<<1, 256>>>((const unsigned*)x);
    k_prep_fwt<<<(OUTC*RES + 255)/256, 256>>>(first_w, first_b);
    k_prep_w1<<<(NL*8192 + 255)/256, 256>>>(conv_w);
    k_prep_w2<<<(NL*4096 + 255)/256, 256>>>(skip_w, out_w);
    k_prep_wtab<<<(TLEN + 255)/256, 256>>>();

    k_upA<<<(BB*CINC*400 + 255)/256, 256>>>(cond, cin_w);
    k_prep_y0<<<BB*NL, 512, SMEM_Y0GEMM>>>(cond_w);

    k_first<<<(BB*TLEN*16 + 255)/256, 256>>>(x);

    dim3 gridL(TLEN/TT, BB);
    for (int l = 0; l < NL; ++l) {
        int d = 1 << (l % 10);
        k_layer<<<gridL, NTL, SMEM_LAYER>>>(l, d,
            conv_b + l*GATE, skip_b + l*SKC, out_b + l*RES);
    }
    dim3 gridF(TLEN/TILE, BB);
    k_final<<<gridF, NTH, SMEM_FINAL>>>(l1w, l1b, l2w, l2b, out);
}

// round 13
// speedup vs baseline: 2.3840x; 2.3840x over previous
#include <cuda_runtime.h>
#include <cuda_fp16.h>
#include <cuda_bf16.h>
#include <cstdint>

#define BB   8
#define TLEN 32000
#define RES  64
#define GATE 128
#define SKC  64
#define CINC 80
#define NL   30
#define OUTC 256
#define TILE 128      /* head kernel time tile */
#define NTH  256      /* head kernel threads */
#define TT   128      /* layer time tile */
#define NTL  512      /* layer kernel threads (16 warps) */

#define AST2 68       /* ACT stride in half2 units (136 halves, conflict-free) */
#define GST  132      /* gate staging stride (floats) */
#define ZST2 36       /* Z stride in half2 units */
#define SM_Z 67584    /* max(ACT 34816, G 67584) */
#define SM_Y0 (SM_Z + TT*ZST2*4)        /* 86016: y0s [8 q][128 ch] floats */
#define SM_WT (SM_Y0 + 4096)            /* 90112: wt float4[128] */
#define SM_WO (SM_WT + 2048)            /* 92160: wo int[128] */
#define SMEM_LAYER (SM_WO + 512)        /* 92672 */
#define SMEM_FINAL (RES*TILE*2*4)       /* 65536 */
#define SMEM_Y0GEMM (128*80*4 + 80*100*4)  /* 72960 */

typedef unsigned int u32;
typedef unsigned long long ull;

/* ---------------- device scratch ---------------- */
__device__ __align__(256) float g_hA[BB*(size_t)TLEN*RES];    // [b][t][64]
__device__ __align__(256) float g_hB[BB*(size_t)TLEN*RES];
__device__ __align__(256) float g_skip[BB*(size_t)TLEN*SKC];  // [b][t][64]
__device__ __align__(256) float g_cA[BB*CINC*400];            // [b][80][400]
__device__ __align__(256) float g_y0[BB*NL*400*128];          // [b][l][frame][ch]
__device__ __align__(256) float4 g_wt4[TLEN];                 // 4-tap upsample weights
__device__ __align__(256) int   g_wbase[TLEN];                // base frame per t
__device__ __align__(256) u32   g_W1pk[NL*8192];   // fp16 frag-packed: [l][ks8][nt16][lane32][2]
__device__ __align__(256) u32   g_W2pk[NL*4096];   // [l][ks4][nt16][lane32][2]
__device__ __align__(256) float g_fwT[OUTC*RES];   // first_w^T + bias
__device__ int g_xflag;

/* ---------------- helpers ---------------- */
__device__ __forceinline__ u32 h2bits(float a, float b) {
    __half2 h = __floats2half2_rn(a, b);
    return *(u32*)&h;
}
__device__ __forceinline__ void mma_f16(float c[4], const u32 a[4], const u32 b[2]) {
    asm volatile("mma.sync.aligned.m16n8k16.row.col.f32.f16.f16.f32 "
        "{%0,%1,%2,%3}, {%4,%5,%6,%7}, {%8,%9}, {%0,%1,%2,%3};"
        : "+f"(c[0]), "+f"(c[1]), "+f"(c[2]), "+f"(c[3])
        : "r"(a[0]), "r"(a[1]), "r"(a[2]), "r"(a[3]), "r"(b[0]), "r"(b[1]));
}
__device__ __forceinline__ float sigf(float x) {
    return __fdividef(1.f, 1.f + __expf(-x));
}
__device__ __forceinline__ float tanhfast(float x) {
    return 2.f * sigf(2.f * x) - 1.f;
}
__device__ __forceinline__ void ffma2(ull& acc, ull ab, ull h2) {
    asm("fma.rn.f32x2 %0, %1, %2, %0;" : "+l"(acc) : "l"(ab), "l"(h2));
}
__device__ __forceinline__ ull pack2(float x) {
    ull r; asm("mov.b64 %0, {%1, %1};" : "=l"(r) : "f"(x)); return r;
}
__device__ __forceinline__ float2 unpack2(ull v) {
    float2 r; asm("mov.b64 {%0, %1}, %2;" : "=f"(r.x), "=f"(r.y) : "l"(v)); return r;
}

/* ---------------- dtype detect ---------------- */
__global__ void k_detect(const unsigned* __restrict__ xu) {
    __shared__ int s_any;
    if (threadIdx.x == 0) s_any = 0;
    __syncthreads();
    int any = 0;
    for (int i = 1 + 2*threadIdx.x; i < BB*TLEN; i += 2*blockDim.x)
        any |= (xu[i] != 0u);
    if (any) atomicOr(&s_any, 1);
    __syncthreads();
    if (threadIdx.x == 0) g_xflag = s_any;
}

/* ---------------- weight prep ---------------- */
__global__ void k_prep_fwt(const float* __restrict__ fw, const float* __restrict__ fb) {
    int i = blockIdx.x*blockDim.x + threadIdx.x;
    if (i >= OUTC*RES) return;
    int xi = i >> 6, o = i & 63;
    g_fwT[i] = fw[o*OUTC + xi] + fb[o];
}

__global__ void k_prep_w1(const float* __restrict__ conv_w) {
    int i = blockIdx.x*blockDim.x + threadIdx.x;
    if (i >= NL*8192) return;
    int l = i / 8192, r = i % 8192;
    int ks = r >> 10, rem = r & 1023;
    int nt = rem >> 6, rem2 = rem & 63;
    int lane = rem2 >> 1, reg = rem2 & 1;
    int k0 = ks*16 + 2*(lane & 3) + 8*reg;   // 0..127 (even)
    int n  = nt*8 + (lane >> 2);
    float f0, f1;
    if (k0 < 64) {
        f0 = conv_w[((l*GATE + n)*RES + k0)*2 + 0];
        f1 = conv_w[((l*GATE + n)*RES + k0 + 1)*2 + 0];
    } else {
        f0 = conv_w[((l*GATE + n)*RES + (k0-64))*2 + 1];
        f1 = conv_w[((l*GATE + n)*RES + (k0-63))*2 + 1];
    }
    g_W1pk[i] = h2bits(f0, f1);
}

__global__ void k_prep_w2(const float* __restrict__ skip_w, const float* __restrict__ out_w) {
    int i = blockIdx.x*blockDim.x + threadIdx.x;
    if (i >= NL*4096) return;
    int l = i / 4096, r = i % 4096;
    int ks = r >> 10, rem = r & 1023;
    int nt = rem >> 6, rem2 = rem & 63;
    int lane = rem2 >> 1, reg = rem2 & 1;
    int k0 = ks*16 + 2*(lane & 3) + 8*reg;   // 0..63 (even)
    int n  = nt*8 + (lane >> 2);
    float f0 = (n < 64) ? skip_w[(l*SKC + n)*64 + k0]
                        : out_w[(l*RES + (n-64))*64 + k0];
    float f1 = (n < 64) ? skip_w[(l*SKC + n)*64 + k0 + 1]
                        : out_w[(l*RES + (n-64))*64 + k0 + 1];
    g_W2pk[i] = h2bits(f0, f1);
}

/* ---- 4-tap composite upsample weights (exact linear impulse of upB+upC) ---- */
__global__ void k_prep_wtab() {
    int t = blockIdx.x*blockDim.x + threadIdx.x;
    if (t >= TLEN) return;
    int lo = t-8 < 0 ? 0 : t-8;
    int hi = t+8 > TLEN-1 ? TLEN-1 : t+8;
    int fmin = 400;
    for (int v = lo; v <= hi; ++v) {
        int tau = v >> 3;
        int jlo = tau-10 < 0 ? 0 : tau-10;
        int f0 = jlo/10;
        if (f0 < fmin) fmin = f0;
    }
    float w0=0.f, w1=0.f, w2=0.f, w3=0.f;
    const float sc = 1.f/(17.f*21.f);
    for (int v = lo; v <= hi; ++v) {
        int tau = v >> 3;
        int jlo = tau-10 < 0 ? 0 : tau-10;
        int jhi = tau+10 > 3999 ? 3999 : tau+10;
        for (int j = jlo; j <= jhi; ++j) {
            int q = j/10 - fmin;
            if (q == 0) w0 += sc;
            else if (q == 1) w1 += sc;
            else if (q == 2) w2 += sc;
            else w3 += sc;
        }
    }
    g_wt4[t] = make_float4(w0, w1, w2, w3);
    g_wbase[t] = fmin;
}

/* ---- y0[b][l][f][ch] = cond_w[l] @ cA[b]  (ch-fast, coalesced) ---- */
__global__ void __launch_bounds__(512) k_prep_y0(const float* __restrict__ cond_w) {
    extern __shared__ float sy[];
    float* s_cwT = sy;            // [80 k][128 ch]
    float* s_ca  = sy + 128*80;   // [80 k][100 f]
    int bl = blockIdx.x;
    int b = bl / NL, l = bl % NL;
    int tid = threadIdx.x;

    for (int i = tid; i < 128*80; i += 512) {
        int ch = i / 80, k = i % 80;
        s_cwT[k*128 + ch] = cond_w[l*GATE*CINC + i];
    }

    for (int ft = 0; ft < 4; ++ft) {
        __syncthreads();
        for (int i = tid; i < 80*100; i += 512) {
            int ch = i / 100, f = i % 100;
            s_ca[ch*100 + f] = g_cA[(b*CINC + ch)*400 + ft*100 + f];
        }
        __syncthreads();
        for (int i = tid; i < 128*100; i += 512) {
            int ch = i & 127, f = i >> 7;
            float s = 0.f;
            #pragma unroll 8
            for (int k = 0; k < 80; ++k)
                s += s_cwT[k*128 + ch] * s_ca[k*100 + f];
            g_y0[((size_t)(b*NL + l)*400 + ft*100 + f)*128 + ch] = s;
        }
    }
}

/* ---------------- first conv + skip reset ([b][t][ch]) ---------------- */
__global__ void k_first(const void* __restrict__ xraw) {
    int idx = blockIdx.x*blockDim.x + threadIdx.x;
    if (idx >= BB*TLEN*16) return;
    int q = idx & 15;
    int g = idx >> 4;
    int t = g % TLEN, b = g / TLEN;
    int xi = g_xflag ? ((const int*)xraw)[g]
                     : (int)(((const long long*)xraw)[g]);
    float4 v = ((const float4*)(g_fwT + xi*64))[q];
    size_t off = ((size_t)b*TLEN + t)*64 + q*4;
    *(float4*)(g_hA + off) = v;
    *(float4*)(g_skip + off) = make_float4(0.f, 0.f, 0.f, 0.f);
}

/* ---------------- conditioning 1x1 (frame domain) ---------------- */
__global__ void k_upA(const float* __restrict__ cond, const float* __restrict__ cin_w) {
    int i = blockIdx.x*blockDim.x + threadIdx.x;
    if (i >= BB*CINC*400) return;
    int f = i % 400, o = (i/400) % CINC, b = i / (CINC*400);
    const float* cp = cond + b*CINC*400 + f;
    const float* wp = cin_w + o*CINC;
    float s = 0.f;
    #pragma unroll 8
    for (int k = 0; k < CINC; ++k) s += wp[k] * cp[k*400];
    g_cA[i] = s;
}

/* ---------------- fp16 mma.sync layer kernel (occ 2, K=128) ---------------- */
__global__ void __launch_bounds__(NTL, 2) k_layer(int l, int d,
        const float* __restrict__ conv_b,
        const float* __restrict__ skip_b,
        const float* __restrict__ out_b) {
    extern __shared__ __align__(16) char smx[];
    u32*   ACT2 = (u32*)smx;               // [128][AST2] half2; becomes G after stage1
    float* G    = (float*)smx;             // [128][GST]
    u32*   Z2   = (u32*)(smx + SM_Z);      // [128][ZST2] half2
    float* s_y0 = (float*)(smx + SM_Y0);   // [8 q][128 ch]
    float4* s_wt = (float4*)(smx + SM_WT); // [128]
    int*   s_wo = (int*)(smx + SM_WO);     // [128]

    int tid = threadIdx.x, lane = tid & 31, wid = tid >> 5;
    int gid = lane >> 2, tig = lane & 3;
    int tg = wid & 3, cg = wid >> 2;       // 4 time-groups x 4 channel-groups
    int b = blockIdx.y, t0 = blockIdx.x * TT;

    const float* hin  = ((l & 1) ? g_hB : g_hA) + (size_t)b*TLEN*64;
    float*       hout = ((l & 1) ? g_hA : g_hB) + (size_t)b*TLEN*64;

    int fbase = g_wbase[t0];

    /* ---- preload y0 frames (coalesced, conflict-free) + weight table ---- */
    if (tid < 128) {
        int t = t0 + tid;
        s_wt[tid] = g_wt4[t];
        s_wo[tid] = g_wbase[t] - fbase;
    }
    {
        const float* y0p = g_y0 + (size_t)(b*NL + l)*400*128;
        for (int i = tid; i < 8*128; i += NTL) {
            int q = i >> 7, ch = i & 127;
            int f = fbase + q;
            s_y0[i] = (f < 400) ? y0p[(size_t)f*128 + ch] : 0.f;
        }
    }

    /* ---- assemble ACT [t][k<128 halves]: hd(64) | h(64), batched LDG ---- */
    #pragma unroll
    for (int it = 0; it < 4; ++it) {
        int idx = tid + it*NTL;
        int t = idx >> 4, q = idx & 15;
        int ts = t0 + t - d;
        float4 v = make_float4(0.f, 0.f, 0.f, 0.f);
        if (ts >= 0) v = *(const float4*)(hin + (size_t)ts*64 + q*4);
        *(uint2*)(ACT2 + t*AST2 + q*2) =
            make_uint2(h2bits(v.x, v.y), h2bits(v.z, v.w));
    }
    #pragma unroll
    for (int it = 0; it < 4; ++it) {
        int idx = tid + it*NTL;
        int t = idx >> 4, q = idx & 15;
        float4 v = *(const float4*)(hin + (size_t)(t0 + t)*64 + q*4);
        *(uint2*)(ACT2 + t*AST2 + (q + 16)*2) =
            make_uint2(h2bits(v.x, v.y), h2bits(v.z, v.w));
    }
    __syncthreads();

    /* ---- stage 1: D1[128 t][128 gate ch], K=128 (8 k-steps) ---- */
    float acc[2][4][4];
    #pragma unroll
    for (int i = 0; i < 2; ++i)
        #pragma unroll
        for (int j = 0; j < 4; ++j)
            #pragma unroll
            for (int r = 0; r < 4; ++r) acc[i][j][r] = 0.f;

    const u32* W1p = g_W1pk + (size_t)l*8192;
    #pragma unroll 1
    for (int ks = 0; ks < 8; ++ks) {
        u32 a[2][4];
        int kk = ks*8 + tig;               // half2 index
        #pragma unroll
        for (int i = 0; i < 2; ++i) {
            int m = (tg*2 + i)*16 + gid;
            a[i][0] = ACT2[m*AST2 + kk];
            a[i][1] = ACT2[(m+8)*AST2 + kk];
            a[i][2] = ACT2[m*AST2 + kk + 4];
            a[i][3] = ACT2[(m+8)*AST2 + kk + 4];
        }
        #pragma unroll
        for (int j = 0; j < 4; ++j) {
            int nt = cg*4 + j;
            uint2 bv = __ldg((const uint2*)(W1p + ((ks*16 + nt)*32 + lane)*2));
            u32 bb[2] = {bv.x, bv.y};
            mma_f16(acc[0][j], a[0], bb);
            mma_f16(acc[1][j], a[1], bb);
        }
    }
    __syncthreads();   /* all ACT reads complete before G overwrite */

    /* ---- epilogue 1: write gates to G ---- */
    #pragma unroll
    for (int i = 0; i < 2; ++i) {
        int m0 = (tg*2 + i)*16 + gid;
        #pragma unroll
        for (int j = 0; j < 4; ++j) {
            int n0 = cg*32 + j*8 + 2*tig;
            *(float2*)&G[m0*GST + n0]     = make_float2(acc[i][j][0], acc[i][j][1]);
            *(float2*)&G[(m0+8)*GST + n0] = make_float2(acc[i][j][2], acc[i][j][3]);
        }
    }
    __syncthreads();

    /* ---- gate: z = tanh(a+cond_a)*sigmoid(b+cond_b) -> Z (half2) ---- */
    for (int idx = tid; idx < TT*32; idx += NTL) {
        int t = idx >> 5, c2 = idx & 31;
        int ch = c2*2;
        float4 w = s_wt[t];
        const float* yq = s_y0 + s_wo[t]*128;
        float ca0 = w.x*yq[ch]       + w.y*yq[128 + ch]       + w.z*yq[256 + ch]       + w.w*yq[384 + ch];
        float ca1 = w.x*yq[ch+1]     + w.y*yq[128 + ch+1]     + w.z*yq[256 + ch+1]     + w.w*yq[384 + ch+1];
        float cb0 = w.x*yq[ch+64]    + w.y*yq[128 + ch+64]    + w.z*yq[256 + ch+64]    + w.w*yq[384 + ch+64];
        float cb1 = w.x*yq[ch+65]    + w.y*yq[128 + ch+65]    + w.z*yq[256 + ch+65]    + w.w*yq[384 + ch+65];
        float a0 = G[t*GST + ch]     + conv_b[ch]     + ca0;
        float a1 = G[t*GST + ch + 1] + conv_b[ch + 1] + ca1;
        float b0 = G[t*GST + 64 + ch]     + conv_b[64 + ch]     + cb0;
        float b1 = G[t*GST + 64 + ch + 1] + conv_b[64 + ch + 1] + cb1;
        Z2[t*ZST2 + c2] = h2bits(tanhfast(a0) * sigf(b0),
                                 tanhfast(a1) * sigf(b1));
    }
    __syncthreads();

    /* ---- stage 2: D2[128 t][skip64|out64], K=64 (4 k-steps) ---- */
    float acc2[2][4][4];
    #pragma unroll
    for (int i = 0; i < 2; ++i)
        #pragma unroll
        for (int j = 0; j < 4; ++j)
            #pragma unroll
            for (int r = 0; r < 4; ++r) acc2[i][j][r] = 0.f;

    const u32* W2p = g_W2pk + (size_t)l*4096;
    #pragma unroll
    for (int ks = 0; ks < 4; ++ks) {
        u32 a[2][4];
        int kk = ks*8 + tig;
        #pragma unroll
        for (int i = 0; i < 2; ++i) {
            int m = (tg*2 + i)*16 + gid;
            a[i][0] = Z2[m*ZST2 + kk];
            a[i][1] = Z2[(m+8)*ZST2 + kk];
            a[i][2] = Z2[m*ZST2 + kk + 4];
            a[i][3] = Z2[(m+8)*ZST2 + kk + 4];
        }
        #pragma unroll
        for (int j = 0; j < 4; ++j) {
            int nt = cg*4 + j;
            uint2 bv = __ldg((const uint2*)(W2p + ((ks*16 + nt)*32 + lane)*2));
            u32 bb[2] = {bv.x, bv.y};
            mma_f16(acc2[0][j], a[0], bb);
            mma_f16(acc2[1][j], a[1], bb);
        }
    }

    /* ---- epilogue 2: skip RMW + residual h ---- */
    #pragma unroll
    for (int i = 0; i < 2; ++i) {
        int m0 = (tg*2 + i)*16 + gid;
        #pragma unroll
        for (int j = 0; j < 4; ++j) {
            int n0 = cg*32 + j*8 + 2*tig;
            #pragma unroll
            for (int h2 = 0; h2 < 2; ++h2) {
                int t = t0 + m0 + 8*h2;
                float v0 = acc2[i][j][2*h2], v1 = acc2[i][j][2*h2 + 1];
                if (n0 < 64) {
                    float2* sp = (float2*)&g_skip[((size_t)b*TLEN + t)*64 + n0];
                    float2 cur = *sp;
                    cur.x += v0 + skip_b[n0];
                    cur.y += v1 + skip_b[n0 + 1];
                    *sp = cur;
                } else {
                    int o = n0 - 64;
                    float2 hv = *(const float2*)&hin[(size_t)t*64 + o];
                    float2 r = make_float2(hv.x + v0 + out_b[o],
                                           hv.y + v1 + out_b[o + 1]);
                    *(float2*)&hout[(size_t)t*64 + o] = r;
                }
            }
        }
    }
}

/* ---------------- output head (FFMA2, transpose-load skip) ---------------- */
__global__ void __launch_bounds__(NTH) k_final(const float* __restrict__ w1,
                                               const float* __restrict__ b1,
                                               const float* __restrict__ w2,
                                               const float* __restrict__ b2,
                                               float* __restrict__ out) {
    extern __shared__ float sm[];
    float* sh_s = sm;              // relu(skips) [64][128]
    float* sh_y = sm + RES*TILE;   // relu(y1)    [64][128]
    int b = blockIdx.y, t0 = blockIdx.x * TILE, tid = threadIdx.x;

    for (int idx = tid; idx < 16*TILE; idx += NTH) {
        int t = idx & (TILE-1), q = idx >> 7;
        float4 v = *(const float4*)(g_skip + ((size_t)b*TLEN + t0 + t)*64 + q*4);
        sh_s[(q*4+0)*TILE + t] = fmaxf(v.x, 0.f);
        sh_s[(q*4+1)*TILE + t] = fmaxf(v.y, 0.f);
        sh_s[(q*4+2)*TILE + t] = fmaxf(v.z, 0.f);
        sh_s[(q*4+3)*TILE + t] = fmaxf(v.w, 0.f);
    }
    __syncthreads();

    int og = tid >> 3, tg = tid & 7;

    {
        ull a0[8], a1[8];
        ull c0 = pack2(b1[og*2]), c1 = pack2(b1[og*2+1]);
        #pragma unroll
        for (int j = 0; j < 8; ++j) { a0[j] = c0; a1[j] = c1; }
        #pragma unroll 4
        for (int r = 0; r < 64; ++r) {
            ull w0 = pack2(w1[(og*2+0)*64 + r]);
            ull w1v = pack2(w1[(og*2+1)*64 + r]);
            const ull* sv = (const ull*)(sh_s + r*TILE) + tg;
            #pragma unroll
            for (int j = 0; j < 8; ++j) {
                ull s = sv[j*8];
                ffma2(a0[j], w0, s);
                ffma2(a1[j], w1v, s);
            }
        }
        #pragma unroll
        for (int j = 0; j < 8; ++j) {
            float2 v0 = unpack2(a0[j]), v1 = unpack2(a1[j]);
            v0.x = fmaxf(v0.x, 0.f); v0.y = fmaxf(v0.y, 0.f);
            v1.x = fmaxf(v1.x, 0.f); v1.y = fmaxf(v1.y, 0.f);
            *(float2*)(sh_y + (og*2+0)*TILE + 2*(tg + 8*j)) = v0;
            *(float2*)(sh_y + (og*2+1)*TILE + 2*(tg + 8*j)) = v1;
        }
    }
    __syncthreads();

    #pragma unroll 1
    for (int p = 0; p < 2; ++p) {
        int ob = p*128 + og*4;
        ull acc[4][8];
        #pragma unroll
        for (int i = 0; i < 4; ++i) {
            ull bi = pack2(b2[ob + i]);
            #pragma unroll
            for (int j = 0; j < 8; ++j) acc[i][j] = bi;
        }
        #pragma unroll 4
        for (int r = 0; r < 64; ++r) {
            ull w0 = pack2(w2[(ob+0)*64 + r]);
            ull w1v = pack2(w2[(ob+1)*64 + r]);
            ull w2v = pack2(w2[(ob+2)*64 + r]);
            ull w3v = pack2(w2[(ob+3)*64 + r]);
            const ull* yv = (const ull*)(sh_y + r*TILE) + tg;
            #pragma unroll
            for (int j = 0; j < 8; ++j) {
                ull y = yv[j*8];
                ffma2(acc[0][j], w0, y);
                ffma2(acc[1][j], w1v, y);
                ffma2(acc[2][j], w2v, y);
                ffma2(acc[3][j], w3v, y);
            }
        }
        #pragma unroll
        for (int i = 0; i < 4; ++i) {
            float2* row = (float2*)(out + ((size_t)b*OUTC + ob + i)*TLEN + t0);
            #pragma unroll
            for (int j = 0; j < 8; ++j)
                row[tg + 8*j] = unpack2(acc[i][j]);
        }
    }
}

/* ---------------- launch ---------------- */
extern "C" void kernel_launch(void* const* d_in, const int* in_sizes, int n_in,
                              void* d_out, int out_size) {
    (void)in_sizes; (void)n_in; (void)out_size;
    const void*  x       = d_in[0];
    const float* cond    = (const float*)d_in[1];
    const float* first_w = (const float*)d_in[2];
    const float* first_b = (const float*)d_in[3];
    const float* cin_w   = (const float*)d_in[4];
    const float* conv_w  = (const float*)d_in[5];
    const float* conv_b  = (const float*)d_in[6];
    const float* cond_w  = (const float*)d_in[7];
    const float* skip_w  = (const float*)d_in[8];
    const float* skip_b  = (const float*)d_in[9];
    const float* out_w   = (const float*)d_in[10];
    const float* out_b   = (const float*)d_in[11];
    const float* l1w     = (const float*)d_in[12];
    const float* l1b     = (const float*)d_in[13];
    const float* l2w     = (const float*)d_in[14];
    const float* l2b     = (const float*)d_in[15];
    float* out = (float*)d_out;

    cudaFuncSetAttribute(k_layer, cudaFuncAttributeMaxDynamicSharedMemorySize, SMEM_LAYER);
    cudaFuncSetAttribute(k_final, cudaFuncAttributeMaxDynamicSharedMemorySize, SMEM_FINAL);
    cudaFuncSetAttribute(k_prep_y0, cudaFuncAttributeMaxDynamicSharedMemorySize, SMEM_Y0GEMM);

    k_detect<<<1, 256>>>((const unsigned*)x);
    k_prep_fwt<<<(OUTC*RES + 255)/256, 256>>>(first_w, first_b);
    k_prep_w1<<<(NL*8192 + 255)/256, 256>>>(conv_w);
    k_prep_w2<<<(NL*4096 + 255)/256, 256>>>(skip_w, out_w);
    k_prep_wtab<<<(TLEN + 255)/256, 256>>>();

    k_upA<<<(BB*CINC*400 + 255)/256, 256>>>(cond, cin_w);
    k_prep_y0<<<BB*NL, 512, SMEM_Y0GEMM>>>(cond_w);

    k_first<<<(BB*TLEN*16 + 255)/256, 256>>>(x);

    dim3 gridL(TLEN/TT, BB);
    for (int l = 0; l < NL; ++l) {
        int d = 1 << (l % 10);
        k_layer<<<gridL, NTL, SMEM_LAYER>>>(l, d,
            conv_b + l*GATE, skip_b + l*SKC, out_b + l*RES);
    }
    dim3 gridF(TLEN/TILE, BB);
    k_final<<<gridF, NTH, SMEM_FINAL>>>(l1w, l1b, l2w, l2b, out);
}

// round 14
// speedup vs baseline: 2.5994x; 1.0904x over previous
#include <cuda_runtime.h>
#include <cuda_fp16.h>
#include <cuda_bf16.h>
#include <cstdint>

#define BB   8
#define TLEN 32000
#define RES  64
#define GATE 128
#define SKC  64
#define CINC 80
#define NL   30
#define OUTC 256
#define TILE 128      /* head kernel time tile */
#define NTH  256      /* head kernel threads */
#define TT   128      /* layer time tile */
#define NTL  512      /* layer kernel threads (16 warps) */

#define AST2 68       /* ACT stride in half2 units (136 halves, conflict-free) */
#define ZST2 36       /* Z stride in half2 units */
#define Y0ST 132      /* y0 smem stride (floats), pad kills cross-frame conflicts */
#define SM_ACT 0                        /* 128*68*4  = 34816 */
#define SM_Z2  34816                    /* 128*36*4  = 18432 */
#define SM_Y0  53248                    /* 8*132*4   = 4224  */
#define SM_WT  57472                    /* 128*16    = 2048  */
#define SM_WO  59520                    /* 128*4     = 512   */
#define SM_CB  60032                    /* 128*4     = 512   */
#define SMEM_LAYER 60544
#define SMEM_FINAL (RES*TILE*2*4)       /* 65536 */
#define SMEM_Y0GEMM (128*80*4 + 80*100*4)  /* 72960 */

typedef unsigned int u32;
typedef unsigned long long ull;

/* ---------------- device scratch ---------------- */
__device__ __align__(256) float g_hA[BB*(size_t)TLEN*RES];    // [b][t][64]
__device__ __align__(256) float g_hB[BB*(size_t)TLEN*RES];
__device__ __align__(256) float g_skip[BB*(size_t)TLEN*SKC];  // [b][t][64]
__device__ __align__(256) float g_cA[BB*CINC*400];            // [b][80][400]
__device__ __align__(256) float g_y0[BB*NL*400*128];          // [b][l][frame][ch]
__device__ __align__(256) float4 g_wt4[TLEN];                 // 4-tap upsample weights
__device__ __align__(256) int   g_wbase[TLEN];                // base frame per t
__device__ __align__(256) u32   g_W1pk[NL*8192];   // fp16 frag-packed: [l][ks8][nt16][lane32][2]
__device__ __align__(256) u32   g_W2pk[NL*4096];   // [l][ks4][nt16][lane32][2]
__device__ __align__(256) float g_fwT[OUTC*RES];   // first_w^T + bias
__device__ int g_xflag;

/* ---------------- helpers ---------------- */
__device__ __forceinline__ u32 h2bits(float a, float b) {
    __half2 h = __floats2half2_rn(a, b);
    return *(u32*)&h;
}
__device__ __forceinline__ void mma_f16(float c[4], const u32 a[4], const u32 b[2]) {
    asm volatile("mma.sync.aligned.m16n8k16.row.col.f32.f16.f16.f32 "
        "{%0,%1,%2,%3}, {%4,%5,%6,%7}, {%8,%9}, {%0,%1,%2,%3};"
        : "+f"(c[0]), "+f"(c[1]), "+f"(c[2]), "+f"(c[3])
        : "r"(a[0]), "r"(a[1]), "r"(a[2]), "r"(a[3]), "r"(b[0]), "r"(b[1]));
}
__device__ __forceinline__ float sigf(float x) {
    return __fdividef(1.f, 1.f + __expf(-x));
}
__device__ __forceinline__ float tanhfast(float x) {
    return 2.f * sigf(2.f * x) - 1.f;
}
__device__ __forceinline__ void ffma2(ull& acc, ull ab, ull h2) {
    asm("fma.rn.f32x2 %0, %1, %2, %0;" : "+l"(acc) : "l"(ab), "l"(h2));
}
__device__ __forceinline__ ull pack2(float x) {
    ull r; asm("mov.b64 %0, {%1, %1};" : "=l"(r) : "f"(x)); return r;
}
__device__ __forceinline__ float2 unpack2(ull v) {
    float2 r; asm("mov.b64 {%0, %1}, %2;" : "=f"(r.x), "=f"(r.y) : "l"(v)); return r;
}

/* ---------------- dtype detect (launch 1) ---------------- */
__global__ void k_detect(const unsigned* __restrict__ xu) {
    __shared__ int s_any;
    if (threadIdx.x == 0) s_any = 0;
    __syncthreads();
    int any = 0;
    for (int i = 1 + 2*threadIdx.x; i < BB*TLEN; i += 2*blockDim.x)
        any |= (xu[i] != 0u);
    if (any) atomicOr(&s_any, 1);
    __syncthreads();
    if (threadIdx.x == 0) g_xflag = s_any;
}

/* ---------------- merged weight prep (launch 2) ---------------- */
#define NP_FWT (OUTC*RES)          /* 16384  */
#define NP_W1  (NL*8192)           /* 245760 */
#define NP_W2  (NL*4096)           /* 122880 */
#define NP_ALL (NP_FWT + NP_W1 + NP_W2 + TLEN)

__global__ void k_prep_all(const float* __restrict__ fw, const float* __restrict__ fb,
                           const float* __restrict__ conv_w,
                           const float* __restrict__ skip_w,
                           const float* __restrict__ out_w) {
    int i = blockIdx.x*blockDim.x + threadIdx.x;
    if (i < NP_FWT) {
        int xi = i >> 6, o = i & 63;
        g_fwT[i] = fw[o*OUTC + xi] + fb[o];
        return;
    }
    i -= NP_FWT;
    if (i < NP_W1) {
        int l = i / 8192, r = i % 8192;
        int ks = r >> 10, rem = r & 1023;
        int nt = rem >> 6, rem2 = rem & 63;
        int lane = rem2 >> 1, reg = rem2 & 1;
        int k0 = ks*16 + 2*(lane & 3) + 8*reg;
        int n  = nt*8 + (lane >> 2);
        float f0, f1;
        if (k0 < 64) {
            f0 = conv_w[((l*GATE + n)*RES + k0)*2 + 0];
            f1 = conv_w[((l*GATE + n)*RES + k0 + 1)*2 + 0];
        } else {
            f0 = conv_w[((l*GATE + n)*RES + (k0-64))*2 + 1];
            f1 = conv_w[((l*GATE + n)*RES + (k0-63))*2 + 1];
        }
        g_W1pk[i] = h2bits(f0, f1);
        return;
    }
    i -= NP_W1;
    if (i < NP_W2) {
        int l = i / 4096, r = i % 4096;
        int ks = r >> 10, rem = r & 1023;
        int nt = rem >> 6, rem2 = rem & 63;
        int lane = rem2 >> 1, reg = rem2 & 1;
        int k0 = ks*16 + 2*(lane & 3) + 8*reg;
        int n  = nt*8 + (lane >> 2);
        float f0 = (n < 64) ? skip_w[(l*SKC + n)*64 + k0]
                            : out_w[(l*RES + (n-64))*64 + k0];
        float f1 = (n < 64) ? skip_w[(l*SKC + n)*64 + k0 + 1]
                            : out_w[(l*RES + (n-64))*64 + k0 + 1];
        g_W2pk[i] = h2bits(f0, f1);
        return;
    }
    i -= NP_W2;
    {   /* upsample weight table */
        int t = i;
        int lo = t-8 < 0 ? 0 : t-8;
        int hi = t+8 > TLEN-1 ? TLEN-1 : t+8;
        int fmin = 400;
        for (int v = lo; v <= hi; ++v) {
            int tau = v >> 3;
            int jlo = tau-10 < 0 ? 0 : tau-10;
            int f0 = jlo/10;
            if (f0 < fmin) fmin = f0;
        }
        float w0=0.f, w1=0.f, w2=0.f, w3=0.f;
        const float sc = 1.f/(17.f*21.f);
        for (int v = lo; v <= hi; ++v) {
            int tau = v >> 3;
            int jlo = tau-10 < 0 ? 0 : tau-10;
            int jhi = tau+10 > 3999 ? 3999 : tau+10;
            for (int j = jlo; j <= jhi; ++j) {
                int q = j/10 - fmin;
                if (q == 0) w0 += sc;
                else if (q == 1) w1 += sc;
                else if (q == 2) w2 += sc;
                else w3 += sc;
            }
        }
        g_wt4[t] = make_float4(w0, w1, w2, w3);
        g_wbase[t] = fmin;
    }
}

/* ---------------- conditioning 1x1, frame domain (launch 3) ---------------- */
__global__ void k_upA(const float* __restrict__ cond, const float* __restrict__ cin_w) {
    int i = blockIdx.x*blockDim.x + threadIdx.x;
    if (i >= BB*CINC*400) return;
    int f = i % 400, o = (i/400) % CINC, b = i / (CINC*400);
    const float* cp = cond + b*CINC*400 + f;
    const float* wp = cin_w + o*CINC;
    float s = 0.f;
    #pragma unroll 8
    for (int k = 0; k < CINC; ++k) s += wp[k] * cp[k*400];
    g_cA[i] = s;
}

/* ---- y0[b][l][f][ch] = cond_w[l] @ cA[b]  (launch 4) ---- */
__global__ void __launch_bounds__(512) k_prep_y0(const float* __restrict__ cond_w) {
    extern __shared__ float sy[];
    float* s_cwT = sy;            // [80 k][128 ch]
    float* s_ca  = sy + 128*80;   // [80 k][100 f]
    int bl = blockIdx.x;
    int b = bl / NL, l = bl % NL;
    int tid = threadIdx.x;

    for (int i = tid; i < 128*80; i += 512) {
        int ch = i / 80, k = i % 80;
        s_cwT[k*128 + ch] = cond_w[l*GATE*CINC + i];
    }

    for (int ft = 0; ft < 4; ++ft) {
        __syncthreads();
        for (int i = tid; i < 80*100; i += 512) {
            int ch = i / 100, f = i % 100;
            s_ca[ch*100 + f] = g_cA[(b*CINC + ch)*400 + ft*100 + f];
        }
        __syncthreads();
        for (int i = tid; i < 128*100; i += 512) {
            int ch = i & 127, f = i >> 7;
            float s = 0.f;
            #pragma unroll 8
            for (int k = 0; k < 80; ++k)
                s += s_cwT[k*128 + ch] * s_ca[k*100 + f];
            g_y0[((size_t)(b*NL + l)*400 + ft*100 + f)*128 + ch] = s;
        }
    }
}

/* ---------------- first conv + skip reset (launch 5) ---------------- */
__global__ void k_first(const void* __restrict__ xraw) {
    int idx = blockIdx.x*blockDim.x + threadIdx.x;
    if (idx >= BB*TLEN*16) return;
    int q = idx & 15;
    int g = idx >> 4;
    int t = g % TLEN, b = g / TLEN;
    int xi = g_xflag ? ((const int*)xraw)[g]
                     : (int)(((const long long*)xraw)[g]);
    float4 v = ((const float4*)(g_fwT + xi*64))[q];
    size_t off = ((size_t)b*TLEN + t)*64 + q*4;
    *(float4*)(g_hA + off) = v;
    *(float4*)(g_skip + off) = make_float4(0.f, 0.f, 0.f, 0.f);
}

/* ---------------- fp16 mma.sync layer kernel (launch 6+: profiled) ---------- */
/* warp cg computes paired gate tiles nt = {2cg, 2cg+1, 8+2cg, 8+2cg+1}:       */
/* acc[.][j] = a(ch), acc[.][j+2] = b(ch) for the SAME (t,ch) in same thread.  */
__global__ void __launch_bounds__(NTL, 2) k_layer(int l, int d,
        const float* __restrict__ conv_b,
        const float* __restrict__ skip_b,
        const float* __restrict__ out_b) {
    extern __shared__ __align__(16) char smx[];
    u32*   ACT2 = (u32*)(smx + SM_ACT);    // [128][AST2] half2
    u32*   Z2   = (u32*)(smx + SM_Z2);     // [128][ZST2] half2
    float* s_y0 = (float*)(smx + SM_Y0);   // [8 q][Y0ST]
    float4* s_wt = (float4*)(smx + SM_WT); // [128]
    int*   s_wo = (int*)(smx + SM_WO);     // [128]
    float* s_cb = (float*)(smx + SM_CB);   // [128] conv_b

    int tid = threadIdx.x, lane = tid & 31, wid = tid >> 5;
    int gid = lane >> 2, tig = lane & 3;
    int tg = wid & 3, cg = wid >> 2;       // 4 time-groups x 4 channel-groups
    int b = blockIdx.y, t0 = blockIdx.x * TT;

    const float* hin  = ((l & 1) ? g_hB : g_hA) + (size_t)b*TLEN*64;
    float*       hout = ((l & 1) ? g_hA : g_hB) + (size_t)b*TLEN*64;

    int fbase = g_wbase[t0];

    /* ---- preload y0 frames, weight table, conv_b ---- */
    if (tid < 128) {
        int t = t0 + tid;
        s_wt[tid] = g_wt4[t];
        s_wo[tid] = g_wbase[t] - fbase;
        s_cb[tid] = conv_b[tid];
    }
    {
        const float* y0p = g_y0 + (size_t)(b*NL + l)*400*128;
        for (int i = tid; i < 8*128; i += NTL) {
            int q = i >> 7, ch = i & 127;
            int f = fbase + q;
            s_y0[q*Y0ST + ch] = (f < 400) ? y0p[(size_t)f*128 + ch] : 0.f;
        }
    }

    /* ---- assemble ACT [t][k<128 halves]: hd(64) | h(64), batched LDG ---- */
    #pragma unroll
    for (int it = 0; it < 4; ++it) {
        int idx = tid + it*NTL;
        int t = idx >> 4, q = idx & 15;
        int ts = t0 + t - d;
        float4 v = make_float4(0.f, 0.f, 0.f, 0.f);
        if (ts >= 0) v = *(const float4*)(hin + (size_t)ts*64 + q*4);
        *(uint2*)(ACT2 + t*AST2 + q*2) =
            make_uint2(h2bits(v.x, v.y), h2bits(v.z, v.w));
    }
    #pragma unroll
    for (int it = 0; it < 4; ++it) {
        int idx = tid + it*NTL;
        int t = idx >> 4, q = idx & 15;
        float4 v = *(const float4*)(hin + (size_t)(t0 + t)*64 + q*4);
        *(uint2*)(ACT2 + t*AST2 + (q + 16)*2) =
            make_uint2(h2bits(v.x, v.y), h2bits(v.z, v.w));
    }
    __syncthreads();   /* sync 1 */

    /* ---- stage 1: D1[128 t][128 gate ch], K=128 (8 k-steps) ---- */
    float acc[2][4][4];
    #pragma unroll
    for (int i = 0; i < 2; ++i)
        #pragma unroll
        for (int j = 0; j < 4; ++j)
            #pragma unroll
            for (int r = 0; r < 4; ++r) acc[i][j][r] = 0.f;

    const u32* W1p = g_W1pk + (size_t)l*8192;
    #pragma unroll 1
    for (int ks = 0; ks < 8; ++ks) {
        u32 a[2][4];
        int kk = ks*8 + tig;               // half2 index
        #pragma unroll
        for (int i = 0; i < 2; ++i) {
            int m = (tg*2 + i)*16 + gid;
            a[i][0] = ACT2[m*AST2 + kk];
            a[i][1] = ACT2[(m+8)*AST2 + kk];
            a[i][2] = ACT2[m*AST2 + kk + 4];
            a[i][3] = ACT2[(m+8)*AST2 + kk + 4];
        }
        #pragma unroll
        for (int j = 0; j < 4; ++j) {
            int nt = (j < 2) ? (cg*2 + j) : (8 + cg*2 + (j - 2));
            uint2 bv = __ldg((const uint2*)(W1p + ((ks*16 + nt)*32 + lane)*2));
            u32 bb[2] = {bv.x, bv.y};
            mma_f16(acc[0][j], a[0], bb);
            mma_f16(acc[1][j], a[1], bb);
        }
    }

    /* ---- gate entirely in registers -> Z2 (half2, stage-2 A layout) ---- */
    #pragma unroll
    for (int i = 0; i < 2; ++i) {
        int mb = (tg*2 + i)*16 + gid;
        #pragma unroll
        for (int rh = 0; rh < 2; ++rh) {
            int t = mb + 8*rh;
            float4 w = s_wt[t];
            const float* yq = s_y0 + s_wo[t]*Y0ST;
            #pragma unroll
            for (int j = 0; j < 2; ++j) {
                int ch0 = cg*16 + 8*j + 2*tig;
                float zz[2];
                #pragma unroll
                for (int col = 0; col < 2; ++col) {
                    int ch = ch0 + col;
                    float ca = w.x*yq[ch]          + w.y*yq[Y0ST + ch]
                             + w.z*yq[2*Y0ST + ch] + w.w*yq[3*Y0ST + ch];
                    float cb = w.x*yq[ch+64]          + w.y*yq[Y0ST + ch+64]
                             + w.z*yq[2*Y0ST + ch+64] + w.w*yq[3*Y0ST + ch+64];
                    int r = 2*rh + col;
                    float av = acc[i][j][r]     + s_cb[ch]      + ca;
                    float bv = acc[i][j+2][r]   + s_cb[ch+64]   + cb;
                    zz[col] = tanhfast(av) * sigf(bv);
                }
                Z2[t*ZST2 + (ch0 >> 1)] = h2bits(zz[0], zz[1]);
            }
        }
    }
    __syncthreads();   /* sync 2 */

    /* ---- stage 2: D2[128 t][skip64|out64], K=64 (4 k-steps) ---- */
    float acc2[2][4][4];
    #pragma unroll
    for (int i = 0; i < 2; ++i)
        #pragma unroll
        for (int j = 0; j < 4; ++j)
            #pragma unroll
            for (int r = 0; r < 4; ++r) acc2[i][j][r] = 0.f;

    const u32* W2p = g_W2pk + (size_t)l*4096;
    #pragma unroll
    for (int ks = 0; ks < 4; ++ks) {
        u32 a[2][4];
        int kk = ks*8 + tig;
        #pragma unroll
        for (int i = 0; i < 2; ++i) {
            int m = (tg*2 + i)*16 + gid;
            a[i][0] = Z2[m*ZST2 + kk];
            a[i][1] = Z2[(m+8)*ZST2 + kk];
            a[i][2] = Z2[m*ZST2 + kk + 4];
            a[i][3] = Z2[(m+8)*ZST2 + kk + 4];
        }
        #pragma unroll
        for (int j = 0; j < 4; ++j) {
            int nt = cg*4 + j;
            uint2 bv = __ldg((const uint2*)(W2p + ((ks*16 + nt)*32 + lane)*2));
            u32 bb[2] = {bv.x, bv.y};
            mma_f16(acc2[0][j], a[0], bb);
            mma_f16(acc2[1][j], a[1], bb);
        }
    }

    /* ---- epilogue 2: skip RMW + residual h ---- */
    #pragma unroll
    for (int i = 0; i < 2; ++i) {
        int m0 = (tg*2 + i)*16 + gid;
        #pragma unroll
        for (int j = 0; j < 4; ++j) {
            int n0 = cg*32 + j*8 + 2*tig;
            #pragma unroll
            for (int h2 = 0; h2 < 2; ++h2) {
                int t = t0 + m0 + 8*h2;
                float v0 = acc2[i][j][2*h2], v1 = acc2[i][j][2*h2 + 1];
                if (n0 < 64) {
                    float2* sp = (float2*)&g_skip[((size_t)b*TLEN + t)*64 + n0];
                    float2 cur = *sp;
                    cur.x += v0 + skip_b[n0];
                    cur.y += v1 + skip_b[n0 + 1];
                    *sp = cur;
                } else {
                    int o = n0 - 64;
                    float2 hv = *(const float2*)&hin[(size_t)t*64 + o];
                    float2 r = make_float2(hv.x + v0 + out_b[o],
                                           hv.y + v1 + out_b[o + 1]);
                    *(float2*)&hout[(size_t)t*64 + o] = r;
                }
            }
        }
    }
}

/* ---------------- output head (FFMA2, transpose-load skip) ---------------- */
__global__ void __launch_bounds__(NTH) k_final(const float* __restrict__ w1,
                                               const float* __restrict__ b1,
                                               const float* __restrict__ w2,
                                               const float* __restrict__ b2,
                                               float* __restrict__ out) {
    extern __shared__ float sm[];
    float* sh_s = sm;              // relu(skips) [64][128]
    float* sh_y = sm + RES*TILE;   // relu(y1)    [64][128]
    int b = blockIdx.y, t0 = blockIdx.x * TILE, tid = threadIdx.x;

    for (int idx = tid; idx < 16*TILE; idx += NTH) {
        int t = idx & (TILE-1), q = idx >> 7;
        float4 v = *(const float4*)(g_skip + ((size_t)b*TLEN + t0 + t)*64 + q*4);
        sh_s[(q*4+0)*TILE + t] = fmaxf(v.x, 0.f);
        sh_s[(q*4+1)*TILE + t] = fmaxf(v.y, 0.f);
        sh_s[(q*4+2)*TILE + t] = fmaxf(v.z, 0.f);
        sh_s[(q*4+3)*TILE + t] = fmaxf(v.w, 0.f);
    }
    __syncthreads();

    int og = tid >> 3, tg = tid & 7;

    {
        ull a0[8], a1[8];
        ull c0 = pack2(b1[og*2]), c1 = pack2(b1[og*2+1]);
        #pragma unroll
        for (int j = 0; j < 8; ++j) { a0[j] = c0; a1[j] = c1; }
        #pragma unroll 4
        for (int r = 0; r < 64; ++r) {
            ull w0 = pack2(w1[(og*2+0)*64 + r]);
            ull w1v = pack2(w1[(og*2+1)*64 + r]);
            const ull* sv = (const ull*)(sh_s + r*TILE) + tg;
            #pragma unroll
            for (int j = 0; j < 8; ++j) {
                ull s = sv[j*8];
                ffma2(a0[j], w0, s);
                ffma2(a1[j], w1v, s);
            }
        }
        #pragma unroll
        for (int j = 0; j < 8; ++j) {
            float2 v0 = unpack2(a0[j]), v1 = unpack2(a1[j]);
            v0.x = fmaxf(v0.x, 0.f); v0.y = fmaxf(v0.y, 0.f);
            v1.x = fmaxf(v1.x, 0.f); v1.y = fmaxf(v1.y, 0.f);
            *(float2*)(sh_y + (og*2+0)*TILE + 2*(tg + 8*j)) = v0;
            *(float2*)(sh_y + (og*2+1)*TILE + 2*(tg + 8*j)) = v1;
        }
    }
    __syncthreads();

    #pragma unroll 1
    for (int p = 0; p < 2; ++p) {
        int ob = p*128 + og*4;
        ull acc[4][8];
        #pragma unroll
        for (int i = 0; i < 4; ++i) {
            ull bi = pack2(b2[ob + i]);
            #pragma unroll
            for (int j = 0; j < 8; ++j) acc[i][j] = bi;
        }
        #pragma unroll 4
        for (int r = 0; r < 64; ++r) {
            ull w0 = pack2(w2[(ob+0)*64 + r]);
            ull w1v = pack2(w2[(ob+1)*64 + r]);
            ull w2v = pack2(w2[(ob+2)*64 + r]);
            ull w3v = pack2(w2[(ob+3)*64 + r]);
            const ull* yv = (const ull*)(sh_y + r*TILE) + tg;
            #pragma unroll
            for (int j = 0; j < 8; ++j) {
                ull y = yv[j*8];
                ffma2(acc[0][j], w0, y);
                ffma2(acc[1][j], w1v, y);
                ffma2(acc[2][j], w2v, y);
                ffma2(acc[3][j], w3v, y);
            }
        }
        #pragma unroll
        for (int i = 0; i < 4; ++i) {
            float2* row = (float2*)(out + ((size_t)b*OUTC + ob + i)*TLEN + t0);
            #pragma unroll
            for (int j = 0; j < 8; ++j)
                row[tg + 8*j] = unpack2(acc[i][j]);
        }
    }
}

/* ---------------- launch ---------------- */
extern "C" void kernel_launch(void* const* d_in, const int* in_sizes, int n_in,
                              void* d_out, int out_size) {
    (void)in_sizes; (void)n_in; (void)out_size;
    const void*  x       = d_in[0];
    const float* cond    = (const float*)d_in[1];
    const float* first_w = (const float*)d_in[2];
    const float* first_b = (const float*)d_in[3];
    const float* cin_w   = (const float*)d_in[4];
    const float* conv_w  = (const float*)d_in[5];
    const float* conv_b  = (const float*)d_in[6];
    const float* cond_w  = (const float*)d_in[7];
    const float* skip_w  = (const float*)d_in[8];
    const float* skip_b  = (const float*)d_in[9];
    const float* out_w   = (const float*)d_in[10];
    const float* out_b   = (const float*)d_in[11];
    const float* l1w     = (const float*)d_in[12];
    const float* l1b     = (const float*)d_in[13];
    const float* l2w     = (const float*)d_in[14];
    const float* l2b     = (const float*)d_in[15];
    float* out = (float*)d_out;

    cudaFuncSetAttribute(k_layer, cudaFuncAttributeMaxDynamicSharedMemorySize, SMEM_LAYER);
    cudaFuncSetAttribute(k_final, cudaFuncAttributeMaxDynamicSharedMemorySize, SMEM_FINAL);
    cudaFuncSetAttribute(k_prep_y0, cudaFuncAttributeMaxDynamicSharedMemorySize, SMEM_Y0GEMM);

    /* launch order fixed so launch #6 (ncu -s 5 -c 1) is k_layer l=0 */
    k_detect<<<1, 256>>>((const unsigned*)x);                             /* 1 */
    k_prep_all<<<(NP_ALL + 255)/256, 256>>>(first_w, first_b,
                                            conv_w, skip_w, out_w);       /* 2 */
    k_upA<<<(BB*CINC*400 + 255)/256, 256>>>(cond, cin_w);                 /* 3 */
    k_prep_y0<<<BB*NL, 512, SMEM_Y0GEMM>>>(cond_w);                       /* 4 */
    k_first<<<(BB*TLEN*16 + 255)/256, 256>>>(x);                          /* 5 */

    dim3 gridL(TLEN/TT, BB);
    for (int l = 0; l < NL; ++l) {
        int d = 1 << (l % 10);
        k_layer<<<gridL, NTL, SMEM_LAYER>>>(l, d,                         /* 6.. */
            conv_b + l*GATE, skip_b + l*SKC, out_b + l*RES);
    }
    dim3 gridF(TLEN/TILE, BB);
    k_final<<<gridF, NTH, SMEM_FINAL>>>(l1w, l1b, l2w, l2b, out);
}

// round 15
// speedup vs baseline: 2.6205x; 1.0081x over previous
#include <cuda_runtime.h>
#include <cuda_fp16.h>
#include <cuda_bf16.h>
#include <cstdint>

#define BB   8
#define TLEN 32000
#define RES  64
#define GATE 128
#define SKC  64
#define CINC 80
#define NL   30
#define OUTC 256
#define TILE 128      /* head kernel time tile */
#define NTH  256      /* head kernel threads */
#define TT   128      /* layer time tile */
#define NTL  512      /* layer kernel threads (16 warps) */

#define AST2 68       /* ACT stride in half2 units (136 halves; 16B row pad) */
#define ZST2 36       /* Z stride in half2 units */
#define Y0ST 132      /* y0 smem stride (floats) */
#define SM_ACT 0                        /* 128*68*4  = 34816 */
#define SM_Z2  34816                    /* 128*36*4  = 18432 */
#define SM_Y0  53248                    /* 8*132*4   = 4224  */
#define SM_WT  57472                    /* 128*16    = 2048  */
#define SM_WO  59520                    /* 128*4     = 512   */
#define SM_CB  60032                    /* 128*4     = 512   */
#define SMEM_LAYER 60544
#define SMEM_FINAL (RES*TILE*2*4)       /* 65536 */
#define SMEM_Y0GEMM (128*80*4 + 80*100*4)  /* 72960 */

typedef unsigned int u32;
typedef unsigned long long ull;

/* ---------------- device scratch ---------------- */
__device__ __align__(256) float g_hA[BB*(size_t)TLEN*RES];    // fp32 h [b][t][64]
__device__ __align__(256) float g_hB[BB*(size_t)TLEN*RES];
__device__ __align__(256) u32   g_h16A[BB*(size_t)TLEN*32];   // fp16 h (half2 words)
__device__ __align__(256) u32   g_h16B[BB*(size_t)TLEN*32];
__device__ __align__(256) float g_skip[BB*(size_t)TLEN*SKC];  // [b][t][64]
__device__ __align__(256) float g_cA[BB*CINC*400];            // [b][80][400]
__device__ __align__(256) float g_y0[BB*NL*400*128];          // [b][l][frame][ch]
__device__ __align__(256) float4 g_wt4[TLEN];                 // 4-tap upsample weights
__device__ __align__(256) int   g_wbase[TLEN];                // base frame per t
__device__ __align__(256) u32   g_W1pk[NL*8192];   // fp16 frag-packed
__device__ __align__(256) u32   g_W2pk[NL*4096];
__device__ __align__(256) float g_fwT[OUTC*RES];   // first_w^T + bias
__device__ int g_xflag;

/* ---------------- helpers ---------------- */
__device__ __forceinline__ u32 h2bits(float a, float b) {
    __half2 h = __floats2half2_rn(a, b);
    return *(u32*)&h;
}
__device__ __forceinline__ void mma_f16(float c[4], const u32 a[4], const u32 b[2]) {
    asm volatile("mma.sync.aligned.m16n8k16.row.col.f32.f16.f16.f32 "
        "{%0,%1,%2,%3}, {%4,%5,%6,%7}, {%8,%9}, {%0,%1,%2,%3};"
        : "+f"(c[0]), "+f"(c[1]), "+f"(c[2]), "+f"(c[3])
        : "r"(a[0]), "r"(a[1]), "r"(a[2]), "r"(a[3]), "r"(b[0]), "r"(b[1]));
}
__device__ __forceinline__ float sigf(float x) {
    return __fdividef(1.f, 1.f + __expf(-x));
}
__device__ __forceinline__ float tanhfast(float x) {
    return 2.f * sigf(2.f * x) - 1.f;
}
__device__ __forceinline__ void ffma2(ull& acc, ull ab, ull h2) {
    asm("fma.rn.f32x2 %0, %1, %2, %0;" : "+l"(acc) : "l"(ab), "l"(h2));
}
__device__ __forceinline__ ull pack2(float x) {
    ull r; asm("mov.b64 %0, {%1, %1};" : "=l"(r) : "f"(x)); return r;
}
__device__ __forceinline__ float2 unpack2(ull v) {
    float2 r; asm("mov.b64 {%0, %1}, %2;" : "=f"(r.x), "=f"(r.y) : "l"(v)); return r;
}
__device__ __forceinline__ u32 smem_u32(const void* p) {
    u32 a;
    asm("{ .reg .u64 t; cvta.to.shared.u64 t, %1; cvt.u32.u64 %0, t; }" : "=r"(a) : "l"(p));
    return a;
}
__device__ __forceinline__ void cp16(u32 dst, const void* src, u32 bytes) {
    asm volatile("cp.async.cg.shared.global [%0], [%1], 16, %2;"
                 :: "r"(dst), "l"(src), "r"(bytes) : "memory");
}

/* ---------------- dtype detect ---------------- */
__global__ void k_detect(const unsigned* __restrict__ xu) {
    __shared__ int s_any;
    if (threadIdx.x == 0) s_any = 0;
    __syncthreads();
    int any = 0;
    for (int i = 1 + 2*threadIdx.x; i < BB*TLEN; i += 2*blockDim.x)
        any |= (xu[i] != 0u);
    if (any) atomicOr(&s_any, 1);
    __syncthreads();
    if (threadIdx.x == 0) g_xflag = s_any;
}

/* ---------------- merged weight prep ---------------- */
#define NP_FWT (OUTC*RES)
#define NP_W1  (NL*8192)
#define NP_W2  (NL*4096)
#define NP_ALL (NP_FWT + NP_W1 + NP_W2 + TLEN)

__global__ void k_prep_all(const float* __restrict__ fw, const float* __restrict__ fb,
                           const float* __restrict__ conv_w,
                           const float* __restrict__ skip_w,
                           const float* __restrict__ out_w) {
    int i = blockIdx.x*blockDim.x + threadIdx.x;
    if (i < NP_FWT) {
        int xi = i >> 6, o = i & 63;
        g_fwT[i] = fw[o*OUTC + xi] + fb[o];
        return;
    }
    i -= NP_FWT;
    if (i < NP_W1) {
        int l = i / 8192, r = i % 8192;
        int ks = r >> 10, rem = r & 1023;
        int nt = rem >> 6, rem2 = rem & 63;
        int lane = rem2 >> 1, reg = rem2 & 1;
        int k0 = ks*16 + 2*(lane & 3) + 8*reg;
        int n  = nt*8 + (lane >> 2);
        float f0, f1;
        if (k0 < 64) {
            f0 = conv_w[((l*GATE + n)*RES + k0)*2 + 0];
            f1 = conv_w[((l*GATE + n)*RES + k0 + 1)*2 + 0];
        } else {
            f0 = conv_w[((l*GATE + n)*RES + (k0-64))*2 + 1];
            f1 = conv_w[((l*GATE + n)*RES + (k0-63))*2 + 1];
        }
        g_W1pk[i] = h2bits(f0, f1);
        return;
    }
    i -= NP_W1;
    if (i < NP_W2) {
        int l = i / 4096, r = i % 4096;
        int ks = r >> 10, rem = r & 1023;
        int nt = rem >> 6, rem2 = rem & 63;
        int lane = rem2 >> 1, reg = rem2 & 1;
        int k0 = ks*16 + 2*(lane & 3) + 8*reg;
        int n  = nt*8 + (lane >> 2);
        float f0 = (n < 64) ? skip_w[(l*SKC + n)*64 + k0]
                            : out_w[(l*RES + (n-64))*64 + k0];
        float f1 = (n < 64) ? skip_w[(l*SKC + n)*64 + k0 + 1]
                            : out_w[(l*RES + (n-64))*64 + k0 + 1];
        g_W2pk[i] = h2bits(f0, f1);
        return;
    }
    i -= NP_W2;
    {   /* upsample weight table */
        int t = i;
        int lo = t-8 < 0 ? 0 : t-8;
        int hi = t+8 > TLEN-1 ? TLEN-1 : t+8;
        int fmin = 400;
        for (int v = lo; v <= hi; ++v) {
            int tau = v >> 3;
            int jlo = tau-10 < 0 ? 0 : tau-10;
            int f0 = jlo/10;
            if (f0 < fmin) fmin = f0;
        }
        float w0=0.f, w1=0.f, w2=0.f, w3=0.f;
        const float sc = 1.f/(17.f*21.f);
        for (int v = lo; v <= hi; ++v) {
            int tau = v >> 3;
            int jlo = tau-10 < 0 ? 0 : tau-10;
            int jhi = tau+10 > 3999 ? 3999 : tau+10;
            for (int j = jlo; j <= jhi; ++j) {
                int q = j/10 - fmin;
                if (q == 0) w0 += sc;
                else if (q == 1) w1 += sc;
                else if (q == 2) w2 += sc;
                else w3 += sc;
            }
        }
        g_wt4[t] = make_float4(w0, w1, w2, w3);
        g_wbase[t] = fmin;
    }
}

/* ---------------- conditioning 1x1 (frame domain) ---------------- */
__global__ void k_upA(const float* __restrict__ cond, const float* __restrict__ cin_w) {
    int i = blockIdx.x*blockDim.x + threadIdx.x;
    if (i >= BB*CINC*400) return;
    int f = i % 400, o = (i/400) % CINC, b = i / (CINC*400);
    const float* cp = cond + b*CINC*400 + f;
    const float* wp = cin_w + o*CINC;
    float s = 0.f;
    #pragma unroll 8
    for (int k = 0; k < CINC; ++k) s += wp[k] * cp[k*400];
    g_cA[i] = s;
}

/* ---- y0[b][l][f][ch] = cond_w[l] @ cA[b]  (f-blocked x4, FFMA2) ---- */
__global__ void __launch_bounds__(512) k_prep_y0(const float* __restrict__ cond_w) {
    extern __shared__ float sy[];
    float* s_cwT = sy;            // [80 k][128 ch]
    float* s_ca  = sy + 128*80;   // [80 k][100 f]
    int bl = blockIdx.x;
    int b = bl / NL, l = bl % NL;
    int tid = threadIdx.x;
    int ch = tid & 127, fq = tid >> 7;   // 4 f-phases

    for (int i = tid; i < 128*80; i += 512) {
        int c = i / 80, k = i % 80;
        s_cwT[k*128 + c] = cond_w[l*GATE*CINC + i];
    }

    for (int ft = 0; ft < 4; ++ft) {
        __syncthreads();
        for (int i = tid; i < 80*100; i += 512) {
            int c = i / 100, f = i % 100;
            s_ca[c*100 + f] = g_cA[(b*CINC + c)*400 + ft*100 + f];
        }
        __syncthreads();
        for (int qd = fq; qd < 25; qd += 4) {    // f0 = 0,4,...,96
            int f0 = qd*4;
            ull a01 = 0, a23 = 0;
            #pragma unroll 4
            for (int k = 0; k < 80; ++k) {
                ull w = pack2(s_cwT[k*128 + ch]);
                const ull* cp = (const ull*)&s_ca[k*100 + f0];  // 16B-aligned, bcast
                ffma2(a01, w, cp[0]);
                ffma2(a23, w, cp[1]);
            }
            float2 v01 = unpack2(a01), v23 = unpack2(a23);
            float* dst = &g_y0[((size_t)(b*NL + l)*400 + ft*100 + f0)*128 + ch];
            dst[0]     = v01.x;
            dst[128]   = v01.y;
            dst[256]   = v23.x;
            dst[384]   = v23.y;
        }
    }
}

/* ---------------- first conv + skip reset + fp16 mirror ---------------- */
__global__ void k_first(const void* __restrict__ xraw) {
    int idx = blockIdx.x*blockDim.x + threadIdx.x;
    if (idx >= BB*TLEN*16) return;
    int q = idx & 15;
    int g = idx >> 4;
    int t = g % TLEN, b = g / TLEN;
    int xi = g_xflag ? ((const int*)xraw)[g]
                     : (int)(((const long long*)xraw)[g]);
    float4 v = ((const float4*)(g_fwT + xi*64))[q];
    size_t off = ((size_t)b*TLEN + t)*64 + q*4;
    *(float4*)(g_hA + off) = v;
    *(float4*)(g_skip + off) = make_float4(0.f, 0.f, 0.f, 0.f);
    *(uint2*)&g_h16A[((size_t)b*TLEN + t)*32 + q*2] =
        make_uint2(h2bits(v.x, v.y), h2bits(v.z, v.w));
}

/* ---------------- fp16 mma.sync layer kernel (occ 2, cp.async ACT) -------- */
__global__ void __launch_bounds__(NTL, 2) k_layer(int l, int d,
        const float* __restrict__ conv_b,
        const float* __restrict__ skip_b,
        const float* __restrict__ out_b) {
    extern __shared__ __align__(16) char smx[];
    u32*   ACT2 = (u32*)(smx + SM_ACT);    // [128][AST2] half2
    u32*   Z2   = (u32*)(smx + SM_Z2);     // [128][ZST2] half2
    float* s_y0 = (float*)(smx + SM_Y0);   // [8 q][Y0ST]
    float4* s_wt = (float4*)(smx + SM_WT); // [128]
    int*   s_wo = (int*)(smx + SM_WO);     // [128]
    float* s_cb = (float*)(smx + SM_CB);   // [128]

    int tid = threadIdx.x, lane = tid & 31, wid = tid >> 5;
    int gid = lane >> 2, tig = lane & 3;
    int tg = wid & 3, cg = wid >> 2;
    int b = blockIdx.y, t0 = blockIdx.x * TT;

    const float* hin   = ((l & 1) ? g_hB : g_hA) + (size_t)b*TLEN*64;
    float*       hout  = ((l & 1) ? g_hA : g_hB) + (size_t)b*TLEN*64;
    const u32*   h16in = ((l & 1) ? g_h16B : g_h16A) + (size_t)b*TLEN*32;
    u32*         h16out= ((l & 1) ? g_h16A : g_h16B) + (size_t)b*TLEN*32;

    /* ---- issue ACT cp.async first (overlap with preloads) ---- */
    u32 act_s = smem_u32(ACT2);
    #pragma unroll
    for (int it = 0; it < 4; ++it) {
        int idx = tid + it*NTL;            // 0..2047
        int t = idx >> 4, c = idx & 15;
        const u32* src;
        u32 bytes = 16;
        if (c < 8) {
            int ts = t0 + t - d;
            src = h16in + (size_t)ts*32 + c*4;
            if (ts < 0) { bytes = 0; src = h16in; }
        } else {
            src = h16in + (size_t)(t0 + t)*32 + (c - 8)*4;
        }
        cp16(act_s + (u32)(t*AST2 + c*4)*4, src, bytes);
    }
    asm volatile("cp.async.commit_group;" ::: "memory");

    int fbase = g_wbase[t0];
    if (tid < 128) {
        int t = t0 + tid;
        s_wt[tid] = g_wt4[t];
        s_wo[tid] = g_wbase[t] - fbase;
        s_cb[tid] = conv_b[tid];
    }
    {
        const float* y0p = g_y0 + (size_t)(b*NL + l)*400*128;
        for (int i = tid; i < 8*128; i += NTL) {
            int q = i >> 7, ch = i & 127;
            int f = fbase + q;
            s_y0[q*Y0ST + ch] = (f < 400) ? y0p[(size_t)f*128 + ch] : 0.f;
        }
    }
    asm volatile("cp.async.wait_group 0;" ::: "memory");
    __syncthreads();   /* sync 1 */

    /* ---- stage 1: D1[128 t][128 gate ch], K=128 (8 k-steps) ---- */
    float acc[2][4][4];
    #pragma unroll
    for (int i = 0; i < 2; ++i)
        #pragma unroll
        for (int j = 0; j < 4; ++j)
            #pragma unroll
            for (int r = 0; r < 4; ++r) acc[i][j][r] = 0.f;

    const u32* W1p = g_W1pk + (size_t)l*8192;
    #pragma unroll 1
    for (int ks = 0; ks < 8; ++ks) {
        u32 a[2][4];
        int kk = ks*8 + tig;
        #pragma unroll
        for (int i = 0; i < 2; ++i) {
            int m = (tg*2 + i)*16 + gid;
            a[i][0] = ACT2[m*AST2 + kk];
            a[i][1] = ACT2[(m+8)*AST2 + kk];
            a[i][2] = ACT2[m*AST2 + kk + 4];
            a[i][3] = ACT2[(m+8)*AST2 + kk + 4];
        }
        #pragma unroll
        for (int j = 0; j < 4; ++j) {
            int nt = (j < 2) ? (cg*2 + j) : (8 + cg*2 + (j - 2));
            uint2 bv = __ldg((const uint2*)(W1p + ((ks*16 + nt)*32 + lane)*2));
            u32 bb[2] = {bv.x, bv.y};
            mma_f16(acc[0][j], a[0], bb);
            mma_f16(acc[1][j], a[1], bb);
        }
    }

    /* ---- gate in registers -> Z2 ---- */
    #pragma unroll
    for (int i = 0; i < 2; ++i) {
        int mb = (tg*2 + i)*16 + gid;
        #pragma unroll
        for (int rh = 0; rh < 2; ++rh) {
            int t = mb + 8*rh;
            float4 w = s_wt[t];
            const float* yq = s_y0 + s_wo[t]*Y0ST;
            #pragma unroll
            for (int j = 0; j < 2; ++j) {
                int ch0 = cg*16 + 8*j + 2*tig;
                float zz[2];
                #pragma unroll
                for (int col = 0; col < 2; ++col) {
                    int ch = ch0 + col;
                    float ca = w.x*yq[ch]          + w.y*yq[Y0ST + ch]
                             + w.z*yq[2*Y0ST + ch] + w.w*yq[3*Y0ST + ch];
                    float cb = w.x*yq[ch+64]          + w.y*yq[Y0ST + ch+64]
                             + w.z*yq[2*Y0ST + ch+64] + w.w*yq[3*Y0ST + ch+64];
                    int r = 2*rh + col;
                    float av = acc[i][j][r]   + s_cb[ch]    + ca;
                    float bv = acc[i][j+2][r] + s_cb[ch+64] + cb;
                    zz[col] = tanhfast(av) * sigf(bv);
                }
                Z2[t*ZST2 + (ch0 >> 1)] = h2bits(zz[0], zz[1]);
            }
        }
    }
    __syncthreads();   /* sync 2 */

    /* ---- stage 2: D2[128 t][skip64|out64], K=64 (4 k-steps) ---- */
    float acc2[2][4][4];
    #pragma unroll
    for (int i = 0; i < 2; ++i)
        #pragma unroll
        for (int j = 0; j < 4; ++j)
            #pragma unroll
            for (int r = 0; r < 4; ++r) acc2[i][j][r] = 0.f;

    const u32* W2p = g_W2pk + (size_t)l*4096;
    #pragma unroll
    for (int ks = 0; ks < 4; ++ks) {
        u32 a[2][4];
        int kk = ks*8 + tig;
        #pragma unroll
        for (int i = 0; i < 2; ++i) {
            int m = (tg*2 + i)*16 + gid;
            a[i][0] = Z2[m*ZST2 + kk];
            a[i][1] = Z2[(m+8)*ZST2 + kk];
            a[i][2] = Z2[m*ZST2 + kk + 4];
            a[i][3] = Z2[(m+8)*ZST2 + kk + 4];
        }
        #pragma unroll
        for (int j = 0; j < 4; ++j) {
            int nt = cg*4 + j;
            uint2 bv = __ldg((const uint2*)(W2p + ((ks*16 + nt)*32 + lane)*2));
            u32 bb[2] = {bv.x, bv.y};
            mma_f16(acc2[0][j], a[0], bb);
            mma_f16(acc2[1][j], a[1], bb);
        }
    }

    /* ---- epilogue 2: skip RMW + residual h (fp32 + fp16 mirror) ---- */
    #pragma unroll
    for (int i = 0; i < 2; ++i) {
        int m0 = (tg*2 + i)*16 + gid;
        #pragma unroll
        for (int j = 0; j < 4; ++j) {
            int n0 = cg*32 + j*8 + 2*tig;
            #pragma unroll
            for (int h2 = 0; h2 < 2; ++h2) {
                int t = t0 + m0 + 8*h2;
                float v0 = acc2[i][j][2*h2], v1 = acc2[i][j][2*h2 + 1];
                if (n0 < 64) {
                    float2* sp = (float2*)&g_skip[((size_t)b*TLEN + t)*64 + n0];
                    float2 cur = *sp;
                    cur.x += v0 + skip_b[n0];
                    cur.y += v1 + skip_b[n0 + 1];
                    *sp = cur;
                } else {
                    int o = n0 - 64;
                    float2 hv = *(const float2*)&hin[(size_t)t*64 + o];
                    float2 r = make_float2(hv.x + v0 + out_b[o],
                                           hv.y + v1 + out_b[o + 1]);
                    *(float2*)&hout[(size_t)t*64 + o] = r;
                    h16out[(size_t)t*32 + (o >> 1)] = h2bits(r.x, r.y);
                }
            }
        }
    }
}

/* ---------------- output head (FFMA2, transpose-load skip) ---------------- */
__global__ void __launch_bounds__(NTH) k_final(const float* __restrict__ w1,
                                               const float* __restrict__ b1,
                                               const float* __restrict__ w2,
                                               const float* __restrict__ b2,
                                               float* __restrict__ out) {
    extern __shared__ float sm[];
    float* sh_s = sm;              // relu(skips) [64][128]
    float* sh_y = sm + RES*TILE;   // relu(y1)    [64][128]
    int b = blockIdx.y, t0 = blockIdx.x * TILE, tid = threadIdx.x;

    for (int idx = tid; idx < 16*TILE; idx += NTH) {
        int t = idx & (TILE-1), q = idx >> 7;
        float4 v = *(const float4*)(g_skip + ((size_t)b*TLEN + t0 + t)*64 + q*4);
        sh_s[(q*4+0)*TILE + t] = fmaxf(v.x, 0.f);
        sh_s[(q*4+1)*TILE + t] = fmaxf(v.y, 0.f);
        sh_s[(q*4+2)*TILE + t] = fmaxf(v.z, 0.f);
        sh_s[(q*4+3)*TILE + t] = fmaxf(v.w, 0.f);
    }
    __syncthreads();

    int og = tid >> 3, tg = tid & 7;

    {
        ull a0[8], a1[8];
        ull c0 = pack2(b1[og*2]), c1 = pack2(b1[og*2+1]);
        #pragma unroll
        for (int j = 0; j < 8; ++j) { a0[j] = c0; a1[j] = c1; }
        #pragma unroll 4
        for (int r = 0; r < 64; ++r) {
            ull w0 = pack2(w1[(og*2+0)*64 + r]);
            ull w1v = pack2(w1[(og*2+1)*64 + r]);
            const ull* sv = (const ull*)(sh_s + r*TILE) + tg;
            #pragma unroll
            for (int j = 0; j < 8; ++j) {
                ull s = sv[j*8];
                ffma2(a0[j], w0, s);
                ffma2(a1[j], w1v, s);
            }
        }
        #pragma unroll
        for (int j = 0; j < 8; ++j) {
            float2 v0 = unpack2(a0[j]), v1 = unpack2(a1[j]);
            v0.x = fmaxf(v0.x, 0.f); v0.y = fmaxf(v0.y, 0.f);
            v1.x = fmaxf(v1.x, 0.f); v1.y = fmaxf(v1.y, 0.f);
            *(float2*)(sh_y + (og*2+0)*TILE + 2*(tg + 8*j)) = v0;
            *(float2*)(sh_y + (og*2+1)*TILE + 2*(tg + 8*j)) = v1;
        }
    }
    __syncthreads();

    #pragma unroll 1
    for (int p = 0; p < 2; ++p) {
        int ob = p*128 + og*4;
        ull acc[4][8];
        #pragma unroll
        for (int i = 0; i < 4; ++i) {
            ull bi = pack2(b2[ob + i]);
            #pragma unroll
            for (int j = 0; j < 8; ++j) acc[i][j] = bi;
        }
        #pragma unroll 4
        for (int r = 0; r < 64; ++r) {
            ull w0 = pack2(w2[(ob+0)*64 + r]);
            ull w1v = pack2(w2[(ob+1)*64 + r]);
            ull w2v = pack2(w2[(ob+2)*64 + r]);
            ull w3v = pack2(w2[(ob+3)*64 + r]);
            const ull* yv = (const ull*)(sh_y + r*TILE) + tg;
            #pragma unroll
            for (int j = 0; j < 8; ++j) {
                ull y = yv[j*8];
                ffma2(acc[0][j], w0, y);
                ffma2(acc[1][j], w1v, y);
                ffma2(acc[2][j], w2v, y);
                ffma2(acc[3][j], w3v, y);
            }
        }
        #pragma unroll
        for (int i = 0; i < 4; ++i) {
            float2* row = (float2*)(out + ((size_t)b*OUTC + ob + i)*TLEN + t0);
            #pragma unroll
            for (int j = 0; j < 8; ++j)
                row[tg + 8*j] = unpack2(acc[i][j]);
        }
    }
}

/* ---------------- launch ---------------- */
extern "C" void kernel_launch(void* const* d_in, const int* in_sizes, int n_in,
                              void* d_out, int out_size) {
    (void)in_sizes; (void)n_in; (void)out_size;
    const void*  x       = d_in[0];
    const float* cond    = (const float*)d_in[1];
    const float* first_w = (const float*)d_in[2];
    const float* first_b = (const float*)d_in[3];
    const float* cin_w   = (const float*)d_in[4];
    const float* conv_w  = (const float*)d_in[5];
    const float* conv_b  = (const float*)d_in[6];
    const float* cond_w  = (const float*)d_in[7];
    const float* skip_w  = (const float*)d_in[8];
    const float* skip_b  = (const float*)d_in[9];
    const float* out_w   = (const float*)d_in[10];
    const float* out_b   = (const float*)d_in[11];
    const float* l1w     = (const float*)d_in[12];
    const float* l1b     = (const float*)d_in[13];
    const float* l2w     = (const float*)d_in[14];
    const float* l2b     = (const float*)d_in[15];
    float* out = (float*)d_out;

    cudaFuncSetAttribute(k_layer, cudaFuncAttributeMaxDynamicSharedMemorySize, SMEM_LAYER);
    cudaFuncSetAttribute(k_final, cudaFuncAttributeMaxDynamicSharedMemorySize, SMEM_FINAL);
    cudaFuncSetAttribute(k_prep_y0, cudaFuncAttributeMaxDynamicSharedMemorySize, SMEM_Y0GEMM);

    k_detect<<<1, 256>>>((const unsigned*)x);
    k_prep_all<<<(NP_ALL + 255)/256, 256>>>(first_w, first_b,
                                            conv_w, skip_w, out_w);
    k_upA<<<(BB*CINC*400 + 255)/256, 256>>>(cond, cin_w);
    k_prep_y0<<<BB*NL, 512, SMEM_Y0GEMM>>>(cond_w);
    k_first<<<(BB*TLEN*16 + 255)/256, 256>>>(x);

    dim3 gridL(TLEN/TT, BB);
    for (int l = 0; l < NL; ++l) {
        int d = 1 << (l % 10);
        k_layer<<<gridL, NTL, SMEM_LAYER>>>(l, d,
            conv_b + l*GATE, skip_b + l*SKC, out_b + l*RES);
    }
    dim3 gridF(TLEN/TILE, BB);
    k_final<<<gridF, NTH, SMEM_FINAL>>>(l1w, l1b, l2w, l2b, out);
}